// round 1
// baseline (speedup 1.0000x reference)
#include <cuda_runtime.h>
#include <math.h>

#define S_LEN 4096
#define D_DIM 512
#define H_NUM 8
#define DH_DIM 64
#define FF_DIM 1024
#define EPS_LN 1e-5f

// ---------------- scratch (no allocations allowed) ----------------
__device__ float g_h   [S_LEN * D_DIM];
__device__ float g_qkv [S_LEN * 3 * D_DIM];
__device__ float g_attn[S_LEN * D_DIM];
__device__ float g_x1  [S_LEN * D_DIM];
__device__ float g_h2  [S_LEN * D_DIM];
__device__ float g_ff  [S_LEN * FF_DIM];

// ---------------- LayerNorm: one block per row (D=512, 256 thr, 2 elems/thr) ----------------
__global__ void ln_kernel(const float* __restrict__ x, const float* __restrict__ g,
                          const float* __restrict__ b, float* __restrict__ out) {
    __shared__ float red[32];
    __shared__ float s_mean, s_rstd;
    int row = blockIdx.x;
    int tid = threadIdx.x;
    const float* xr = x + (size_t)row * D_DIM;
    float2 v = *(const float2*)(xr + tid * 2);

    float sum = v.x + v.y;
    #pragma unroll
    for (int o = 16; o > 0; o >>= 1) sum += __shfl_down_sync(0xffffffffu, sum, o);
    if ((tid & 31) == 0) red[tid >> 5] = sum;
    __syncthreads();
    if (tid < 32) {
        float t = (tid < 8) ? red[tid] : 0.f;
        #pragma unroll
        for (int o = 4; o > 0; o >>= 1) t += __shfl_down_sync(0xffffffffu, t, o);
        if (tid == 0) s_mean = t * (1.f / D_DIM);
    }
    __syncthreads();
    float mean = s_mean;
    float d0 = v.x - mean, d1 = v.y - mean;

    float vs = d0 * d0 + d1 * d1;
    #pragma unroll
    for (int o = 16; o > 0; o >>= 1) vs += __shfl_down_sync(0xffffffffu, vs, o);
    if ((tid & 31) == 0) red[tid >> 5] = vs;
    __syncthreads();
    if (tid < 32) {
        float t = (tid < 8) ? red[tid] : 0.f;
        #pragma unroll
        for (int o = 4; o > 0; o >>= 1) t += __shfl_down_sync(0xffffffffu, t, o);
        if (tid == 0) s_rstd = rsqrtf(t * (1.f / D_DIM) + EPS_LN);
    }
    __syncthreads();
    float rstd = s_rstd;

    int c = tid * 2;
    float2 gg = *(const float2*)(g + c);
    float2 bb = *(const float2*)(b + c);
    float2 o2;
    o2.x = d0 * rstd * gg.x + bb.x;
    o2.y = d1 * rstd * gg.y + bb.y;
    *(float2*)(out + (size_t)row * D_DIM + c) = o2;
}

// ---------------- GEMM: C[M,N] = A[M,K] @ B[K,N] + bias, 128x128x8 tile, 8x8/thread ----------------
// EPI: 0 = bias only, 1 = bias + exact GELU, 2 = bias + residual add
template <int EPI>
__global__ void __launch_bounds__(256, 2)
gemm_kernel(const float* __restrict__ A, const float* __restrict__ B,
            const float* __restrict__ bias, const float* __restrict__ res,
            float* __restrict__ C, int M, int N, int K) {
    __shared__ float As[8][132];
    __shared__ float Bs[8][132];
    int tid = threadIdx.x;
    int tx = tid & 15, ty = tid >> 4;
    int bm = blockIdx.y * 128, bn = blockIdx.x * 128;

    float acc[8][8];
    #pragma unroll
    for (int i = 0; i < 8; i++)
        #pragma unroll
        for (int j = 0; j < 8; j++) acc[i][j] = 0.f;

    int a_row = tid >> 1;          // 0..127
    int a_col = (tid & 1) * 4;     // 0 or 4
    int b_row = tid >> 5;          // 0..7
    int b_col = (tid & 31) * 4;    // 0..124
    const float* Ap = A + (size_t)(bm + a_row) * K + a_col;
    const float* Bp = B + (size_t)b_row * N + bn + b_col;

    for (int k0 = 0; k0 < K; k0 += 8) {
        float4 av = *(const float4*)Ap;
        float4 bv = *(const float4*)Bp;
        Ap += 8;
        Bp += (size_t)8 * N;
        As[a_col + 0][a_row] = av.x;
        As[a_col + 1][a_row] = av.y;
        As[a_col + 2][a_row] = av.z;
        As[a_col + 3][a_row] = av.w;
        *(float4*)&Bs[b_row][b_col] = bv;
        __syncthreads();
        #pragma unroll
        for (int k = 0; k < 8; k++) {
            float af[8], bf[8];
            *(float4*)&af[0] = *(const float4*)&As[k][ty * 8];
            *(float4*)&af[4] = *(const float4*)&As[k][ty * 8 + 4];
            *(float4*)&bf[0] = *(const float4*)&Bs[k][tx * 8];
            *(float4*)&bf[4] = *(const float4*)&Bs[k][tx * 8 + 4];
            #pragma unroll
            for (int i = 0; i < 8; i++)
                #pragma unroll
                for (int j = 0; j < 8; j++)
                    acc[i][j] = fmaf(af[i], bf[j], acc[i][j]);
        }
        __syncthreads();
    }

    int row = bm + ty * 8, col = bn + tx * 8;
    #pragma unroll
    for (int i = 0; i < 8; i++) {
        float* cp = C + (size_t)(row + i) * N + col;
        const float* rp = (EPI == 2) ? (res + (size_t)(row + i) * N + col) : nullptr;
        #pragma unroll
        for (int j = 0; j < 8; j++) {
            float v = acc[i][j] + bias[col + j];
            if (EPI == 1) v = 0.5f * v * (1.f + erff(v * 0.70710678118654752f));
            if (EPI == 2) v = v + rp[j];
            cp[j] = v;
        }
    }
}

// ---------------- Flash attention (causal): blocks of 64 queries x one head ----------------
// qkv layout per row: [3, H, DH] contiguous (q at h*64, k at 512+h*64, v at 1024+h*64)
#define SQ_STR 65
#define SV_STR 68
#define ATTN_SMEM_FLOATS (3 * 64 * SQ_STR + 64 * SV_STR + 3 * 64)

__global__ void attn_kernel(const float* __restrict__ qkv, float* __restrict__ out) {
    extern __shared__ float sm[];
    float* sQ = sm;                        // 64 x 65
    float* sK = sQ + 64 * SQ_STR;          // 64 x 65
    float* sS = sK + 64 * SQ_STR;          // 64 x 65
    float* sV = sS + 64 * SQ_STR;          // 64 x 68
    float* sM = sV + 64 * SV_STR;
    float* sL = sM + 64;
    float* sA = sL + 64;

    int qb = blockIdx.x, h = blockIdx.y;
    int tid = threadIdx.x;
    int tx = tid & 15, ty = tid >> 4;

    // load Q tile
    for (int i = tid; i < 64 * 16; i += 256) {
        int r = i >> 4, c = (i & 15) << 2;
        float4 v = *(const float4*)(qkv + (size_t)(qb * 64 + r) * 1536 + h * 64 + c);
        float* q = sQ + r * SQ_STR + c;
        q[0] = v.x; q[1] = v.y; q[2] = v.z; q[3] = v.w;
    }
    if (tid < 64) { sM[tid] = -1e30f; sL[tid] = 0.f; }

    float acc[4][4];
    #pragma unroll
    for (int i = 0; i < 4; i++)
        #pragma unroll
        for (int j = 0; j < 4; j++) acc[i][j] = 0.f;

    for (int kb = 0; kb <= qb; kb++) {
        __syncthreads();  // protect smem from previous iteration's readers
        for (int i = tid; i < 64 * 16; i += 256) {
            int r = i >> 4, c = (i & 15) << 2;
            const float* base = qkv + (size_t)(kb * 64 + r) * 1536 + h * 64 + c;
            float4 kv = *(const float4*)(base + 512);
            float4 vv = *(const float4*)(base + 1024);
            float* kd = sK + r * SQ_STR + c;
            kd[0] = kv.x; kd[1] = kv.y; kd[2] = kv.z; kd[3] = kv.w;
            float* vd = sV + r * SV_STR + c;
            vd[0] = vv.x; vd[1] = vv.y; vd[2] = vv.z; vd[3] = vv.w;
        }
        __syncthreads();

        // S = Q K^T / sqrt(DH), 4x4 per thread over (q=ty*4.., k=tx*4..)
        float s[4][4];
        #pragma unroll
        for (int i = 0; i < 4; i++)
            #pragma unroll
            for (int j = 0; j < 4; j++) s[i][j] = 0.f;
        #pragma unroll 4
        for (int d = 0; d < 64; d++) {
            float a[4], bq[4];
            #pragma unroll
            for (int i = 0; i < 4; i++) a[i]  = sQ[(ty * 4 + i) * SQ_STR + d];
            #pragma unroll
            for (int j = 0; j < 4; j++) bq[j] = sK[(tx * 4 + j) * SQ_STR + d];
            #pragma unroll
            for (int i = 0; i < 4; i++)
                #pragma unroll
                for (int j = 0; j < 4; j++)
                    s[i][j] = fmaf(a[i], bq[j], s[i][j]);
        }
        bool diag = (kb == qb);
        #pragma unroll
        for (int i = 0; i < 4; i++)
            #pragma unroll
            for (int j = 0; j < 4; j++) {
                float val = s[i][j] * 0.125f;
                if (diag && (tx * 4 + j) > (ty * 4 + i)) val = -1e30f;
                sS[(ty * 4 + i) * SQ_STR + tx * 4 + j] = val;
            }
        __syncthreads();

        // online softmax row pass: one thread per query row
        if (tid < 64) {
            float m = sM[tid];
            float mn = m;
            float* srow = sS + tid * SQ_STR;
            #pragma unroll 8
            for (int j = 0; j < 64; j++) mn = fmaxf(mn, srow[j]);
            float alpha = __expf(m - mn);
            float l = sL[tid] * alpha;
            #pragma unroll 8
            for (int j = 0; j < 64; j++) {
                float p = __expf(srow[j] - mn);
                srow[j] = p;
                l += p;
            }
            sM[tid] = mn; sL[tid] = l; sA[tid] = alpha;
        }
        __syncthreads();

        // rescale O, then O += P @ V   (4 q rows x 4 d cols per thread)
        float al[4];
        #pragma unroll
        for (int i = 0; i < 4; i++) al[i] = sA[ty * 4 + i];
        #pragma unroll
        for (int i = 0; i < 4; i++)
            #pragma unroll
            for (int j = 0; j < 4; j++) acc[i][j] *= al[i];
        #pragma unroll 4
        for (int kk = 0; kk < 64; kk++) {
            float p[4];
            #pragma unroll
            for (int i = 0; i < 4; i++) p[i] = sS[(ty * 4 + i) * SQ_STR + kk];
            float4 vv = *(const float4*)(sV + kk * SV_STR + tx * 4);
            #pragma unroll
            for (int i = 0; i < 4; i++) {
                acc[i][0] = fmaf(p[i], vv.x, acc[i][0]);
                acc[i][1] = fmaf(p[i], vv.y, acc[i][1]);
                acc[i][2] = fmaf(p[i], vv.z, acc[i][2]);
                acc[i][3] = fmaf(p[i], vv.w, acc[i][3]);
            }
        }
    }

    float inv[4];
    #pragma unroll
    for (int i = 0; i < 4; i++) inv[i] = 1.f / sL[ty * 4 + i];
    #pragma unroll
    for (int i = 0; i < 4; i++) {
        float* op = out + (size_t)(qb * 64 + ty * 4 + i) * D_DIM + h * 64 + tx * 4;
        #pragma unroll
        for (int j = 0; j < 4; j++) op[j] = acc[i][j] * inv[i];
    }
}

// ---------------- launch ----------------
extern "C" void kernel_launch(void* const* d_in, const int* in_sizes, int n_in,
                              void* d_out, int out_size) {
    const float* x    = (const float*)d_in[0];
    const float* wqkv = (const float*)d_in[1];
    const float* bqkv = (const float*)d_in[2];
    const float* wout = (const float*)d_in[3];
    const float* bout = (const float*)d_in[4];
    const float* wff1 = (const float*)d_in[5];
    const float* bff1 = (const float*)d_in[6];
    const float* wff2 = (const float*)d_in[7];
    const float* bff2 = (const float*)d_in[8];
    const float* g1   = (const float*)d_in[9];
    const float* bt1  = (const float*)d_in[10];
    const float* g2   = (const float*)d_in[11];
    const float* bt2  = (const float*)d_in[12];
    float* out = (float*)d_out;

    float *ph, *pqkv, *pattn, *px1, *ph2, *pff;
    cudaGetSymbolAddress((void**)&ph,    g_h);
    cudaGetSymbolAddress((void**)&pqkv,  g_qkv);
    cudaGetSymbolAddress((void**)&pattn, g_attn);
    cudaGetSymbolAddress((void**)&px1,   g_x1);
    cudaGetSymbolAddress((void**)&ph2,   g_h2);
    cudaGetSymbolAddress((void**)&pff,   g_ff);

    int smem = ATTN_SMEM_FLOATS * (int)sizeof(float);
    cudaFuncSetAttribute(attn_kernel, cudaFuncAttributeMaxDynamicSharedMemorySize, smem);

    // 1) h = LN1(x)
    ln_kernel<<<S_LEN, 256>>>(x, g1, bt1, ph);
    // 2) qkv = h @ w_qkv + b_qkv         [4096 x 1536]
    gemm_kernel<0><<<dim3(12, 32), 256>>>(ph, wqkv, bqkv, nullptr, pqkv, S_LEN, 3 * D_DIM, D_DIM);
    // 3) attn_out = causal softmax(QK^T/8) @ V
    attn_kernel<<<dim3(S_LEN / 64, H_NUM), 256, smem>>>(pqkv, pattn);
    // 4) x1 = x + attn_out @ w_out + b_out
    gemm_kernel<2><<<dim3(4, 32), 256>>>(pattn, wout, bout, x, px1, S_LEN, D_DIM, D_DIM);
    // 5) h2 = LN2(x1)
    ln_kernel<<<S_LEN, 256>>>(px1, g2, bt2, ph2);
    // 6) ff = gelu(h2 @ w_ff1 + b_ff1)   [4096 x 1024]
    gemm_kernel<1><<<dim3(8, 32), 256>>>(ph2, wff1, bff1, nullptr, pff, S_LEN, FF_DIM, D_DIM);
    // 7) out = x1 + ff @ w_ff2 + b_ff2
    gemm_kernel<2><<<dim3(4, 32), 256>>>(pff, wff2, bff2, px1, out, S_LEN, D_DIM, FF_DIM);
}

// round 3
// speedup vs baseline: 1.3130x; 1.3130x over previous
#include <cuda_runtime.h>
#include <cuda_bf16.h>
#include <math.h>
#include <stdint.h>

#define S_LEN 4096
#define D_DIM 512
#define H_NUM 8
#define FF_DIM 1024
#define EPS_LN 1e-5f

// ---------------- scratch (no allocations allowed) ----------------
__device__ float g_h   [S_LEN * D_DIM];
__device__ float g_qkv [S_LEN * 3 * D_DIM];
__device__ float g_attn[S_LEN * D_DIM];
__device__ float g_x1  [S_LEN * D_DIM];
__device__ float g_h2  [S_LEN * D_DIM];
__device__ float g_ff  [S_LEN * FF_DIM];

__device__ __forceinline__ uint32_t smem_u32(const void* p) {
    uint32_t a;
    asm("{ .reg .u64 t; cvta.to.shared.u64 t, %1; cvt.u32.u64 %0, t; }" : "=r"(a) : "l"(p));
    return a;
}

#define LDMATRIX_X4(r0, r1, r2, r3, a) \
    asm volatile("ldmatrix.sync.aligned.m8n8.x4.shared.b16 {%0,%1,%2,%3}, [%4];" \
        : "=r"(r0), "=r"(r1), "=r"(r2), "=r"(r3) : "r"(a))
#define LDMATRIX_X2(r0, r1, a) \
    asm volatile("ldmatrix.sync.aligned.m8n8.x2.shared.b16 {%0,%1}, [%2];" \
        : "=r"(r0), "=r"(r1) : "r"(a))
#define MMA_BF16(d, a, b) \
    asm volatile("mma.sync.aligned.m16n8k16.row.col.f32.bf16.bf16.f32 " \
        "{%0,%1,%2,%3}, {%4,%5,%6,%7}, {%8,%9}, {%0,%1,%2,%3};" \
        : "+f"((d)[0]), "+f"((d)[1]), "+f"((d)[2]), "+f"((d)[3]) \
        : "r"((a)[0]), "r"((a)[1]), "r"((a)[2]), "r"((a)[3]), "r"((b)[0]), "r"((b)[1]))

// split a float4 into hi/lo bf16 pairs (2x u32 each)
__device__ __forceinline__ void split_bf16(float4 v, uint2& hp, uint2& lp) {
    __nv_bfloat162 h01 = __floats2bfloat162_rn(v.x, v.y);
    __nv_bfloat162 h23 = __floats2bfloat162_rn(v.z, v.w);
    float lx = v.x - __bfloat162float(__low2bfloat16(h01));
    float ly = v.y - __bfloat162float(__high2bfloat16(h01));
    float lz = v.z - __bfloat162float(__low2bfloat16(h23));
    float lw = v.w - __bfloat162float(__high2bfloat16(h23));
    __nv_bfloat162 l01 = __floats2bfloat162_rn(lx, ly);
    __nv_bfloat162 l23 = __floats2bfloat162_rn(lz, lw);
    hp.x = *(uint32_t*)&h01; hp.y = *(uint32_t*)&h23;
    lp.x = *(uint32_t*)&l01; lp.y = *(uint32_t*)&l23;
}

// ---------------- LayerNorm ----------------
__global__ void ln_kernel(const float* __restrict__ x, const float* __restrict__ g,
                          const float* __restrict__ b, float* __restrict__ out) {
    __shared__ float red[32];
    __shared__ float s_mean, s_rstd;
    int row = blockIdx.x;
    int tid = threadIdx.x;
    const float* xr = x + (size_t)row * D_DIM;
    float2 v = *(const float2*)(xr + tid * 2);

    float sum = v.x + v.y;
    #pragma unroll
    for (int o = 16; o > 0; o >>= 1) sum += __shfl_down_sync(0xffffffffu, sum, o);
    if ((tid & 31) == 0) red[tid >> 5] = sum;
    __syncthreads();
    if (tid < 32) {
        float t = (tid < 8) ? red[tid] : 0.f;
        #pragma unroll
        for (int o = 4; o > 0; o >>= 1) t += __shfl_down_sync(0xffffffffu, t, o);
        if (tid == 0) s_mean = t * (1.f / D_DIM);
    }
    __syncthreads();
    float mean = s_mean;
    float d0 = v.x - mean, d1 = v.y - mean;

    float vs = d0 * d0 + d1 * d1;
    #pragma unroll
    for (int o = 16; o > 0; o >>= 1) vs += __shfl_down_sync(0xffffffffu, vs, o);
    if ((tid & 31) == 0) red[tid >> 5] = vs;
    __syncthreads();
    if (tid < 32) {
        float t = (tid < 8) ? red[tid] : 0.f;
        #pragma unroll
        for (int o = 4; o > 0; o >>= 1) t += __shfl_down_sync(0xffffffffu, t, o);
        if (tid == 0) s_rstd = rsqrtf(t * (1.f / D_DIM) + EPS_LN);
    }
    __syncthreads();
    float rstd = s_rstd;

    int c = tid * 2;
    float2 gg = *(const float2*)(g + c);
    float2 bb = *(const float2*)(b + c);
    float2 o2;
    o2.x = d0 * rstd * gg.x + bb.x;
    o2.y = d1 * rstd * gg.y + bb.y;
    *(float2*)(out + (size_t)row * D_DIM + c) = o2;
}

// ---------------- mma.sync split-bf16 GEMM ----------------
// C[M,N] = A[M,K] @ B[K,N] + bias (+EPI).  BM=128, BK=32, BN template.
// smem rows have 80-byte stride (40 halves) -> ldmatrix conflict-free.
// EPI: 0=bias, 1=bias+GELU(exact), 2=bias+residual
template <int BN, int K_TOT, int EPI>
__global__ void __launch_bounds__(256)
gemm_mma(const float* __restrict__ A, const float* __restrict__ B,
         const float* __restrict__ bias, const float* __restrict__ res,
         float* __restrict__ C, int N) {
    constexpr int WARPS_N = BN / 32;          // 4 or 2
    constexpr int WARPS_M = 8 / WARPS_N;      // 2 or 4
    constexpr int WM = 128 / WARPS_M;         // 64 or 32
    constexpr int MI = WM / 16;               // 4 or 2
    constexpr int A_BYTES = 128 * 80;
    constexpr int B_BYTES = BN * 80;
    constexpr int NS = K_TOT / 32;

    __shared__ __align__(16) char sm[2 * A_BYTES + 2 * B_BYTES];

    const uint32_t sbase = smem_u32(sm);
    const uint32_t sAh = sbase;
    const uint32_t sAl = sbase + A_BYTES;
    const uint32_t sBh = sbase + 2 * A_BYTES;
    const uint32_t sBl = sBh + B_BYTES;

    int tid = threadIdx.x;
    int wid = tid >> 5;
    int l = tid & 31;
    int bm = blockIdx.y * 128, bn = blockIdx.x * BN;
    int warp_m = wid / WARPS_N, warp_n = wid % WARPS_N;

    float d[MI][4][4];
    #pragma unroll
    for (int i = 0; i < MI; i++)
        #pragma unroll
        for (int j = 0; j < 4; j++)
            #pragma unroll
            for (int k = 0; k < 4; k++) d[i][j][k] = 0.f;

    // loader indices
    int a_row = tid >> 1;
    int a_cb = (tid & 1) * 16;
    int b_nb = tid % (BN / 4);
    int b_kb = tid / (BN / 4);          // 0..7 (BN=128) / 0..15(BN=64, only <8 used)

    // ldmatrix addresses (byte offsets into hi arrays; lo = +A_BYTES / +B_BYTES)
    int lb = l & 15;
    uint32_t a_lm = sAh + (uint32_t)(warp_m * WM + lb) * 80 + (uint32_t)(l >> 4) * 16;
    uint32_t b_lm = sBh + (uint32_t)(warp_n * 32 + (lb & 7)) * 80 + (uint32_t)(lb >> 3) * 16;

    for (int s = 0; s < NS; s++) {
        int k0 = s * 32;
        __syncthreads();
        // ---- A: 128 x 32, 2 threads/row, 16 floats each ----
        {
            const float* ap = A + (size_t)(bm + a_row) * K_TOT + k0 + a_cb;
            uint32_t base = (uint32_t)(a_row * 80 + a_cb * 2);
            #pragma unroll
            for (int i = 0; i < 4; i++) {
                float4 v = *(const float4*)(ap + i * 4);
                uint2 hp, lp;
                split_bf16(v, hp, lp);
                *(uint2*)(sm + base + i * 8) = hp;
                *(uint2*)(sm + A_BYTES + base + i * 8) = lp;
            }
        }
        // ---- B: BN x 32 transposed from [k][n], 4x4 blocks ----
        if (BN == 128 || tid < 128) {
            const float* bp = B + (size_t)(k0 + b_kb * 4) * N + bn + b_nb * 4;
            float4 r0 = *(const float4*)(bp);
            float4 r1 = *(const float4*)(bp + N);
            float4 r2 = *(const float4*)(bp + 2 * N);
            float4 r3 = *(const float4*)(bp + 3 * N);
            float4 cols[4] = {
                {r0.x, r1.x, r2.x, r3.x},
                {r0.y, r1.y, r2.y, r3.y},
                {r0.z, r1.z, r2.z, r3.z},
                {r0.w, r1.w, r2.w, r3.w}};
            #pragma unroll
            for (int nn = 0; nn < 4; nn++) {
                uint2 hp, lp;
                split_bf16(cols[nn], hp, lp);
                uint32_t off = (uint32_t)((b_nb * 4 + nn) * 80 + b_kb * 8);
                *(uint2*)(sm + 2 * A_BYTES + off) = hp;
                *(uint2*)(sm + 2 * A_BYTES + B_BYTES + off) = lp;
            }
        }
        __syncthreads();

        // ---- compute: 2 k-steps of 16 ----
        #pragma unroll
        for (int ks = 0; ks < 2; ks++) {
            uint32_t bh[4][2], bl[4][2];
            #pragma unroll
            for (int nj = 0; nj < 4; nj++) {
                uint32_t ba = b_lm + nj * 8 * 80 + ks * 32;
                LDMATRIX_X2(bh[nj][0], bh[nj][1], ba);
                LDMATRIX_X2(bl[nj][0], bl[nj][1], ba + B_BYTES);
            }
            #pragma unroll
            for (int mi = 0; mi < MI; mi++) {
                uint32_t ah[4], al[4];
                uint32_t aa = a_lm + mi * 16 * 80 + ks * 32;
                LDMATRIX_X4(ah[0], ah[1], ah[2], ah[3], aa);
                LDMATRIX_X4(al[0], al[1], al[2], al[3], aa + A_BYTES);
                #pragma unroll
                for (int nj = 0; nj < 4; nj++) {
                    MMA_BF16(d[mi][nj], ah, bh[nj]);
                    MMA_BF16(d[mi][nj], ah, bl[nj]);
                    MMA_BF16(d[mi][nj], al, bh[nj]);
                }
            }
        }
    }

    // ---- epilogue ----
    #pragma unroll
    for (int mi = 0; mi < MI; mi++) {
        int row0 = bm + warp_m * WM + mi * 16 + (l >> 2);
        #pragma unroll
        for (int nj = 0; nj < 4; nj++) {
            int col = bn + warp_n * 32 + nj * 8 + (l & 3) * 2;
            float2 bb = *(const float2*)(bias + col);
            #pragma unroll
            for (int half = 0; half < 2; half++) {
                int row = row0 + half * 8;
                float vx = d[mi][nj][half * 2 + 0] + bb.x;
                float vy = d[mi][nj][half * 2 + 1] + bb.y;
                if (EPI == 1) {
                    vx = 0.5f * vx * (1.f + erff(vx * 0.70710678118654752f));
                    vy = 0.5f * vy * (1.f + erff(vy * 0.70710678118654752f));
                }
                if (EPI == 2) {
                    float2 rr = *(const float2*)(res + (size_t)row * N + col);
                    vx += rr.x; vy += rr.y;
                }
                float2 o2; o2.x = vx; o2.y = vy;
                *(float2*)(C + (size_t)row * N + col) = o2;
            }
        }
    }
}

// ---------------- Flash attention (validated R1 version) ----------------
#define SQ_STR 65
#define SV_STR 68
#define ATTN_SMEM_FLOATS (3 * 64 * SQ_STR + 64 * SV_STR + 3 * 64)

__global__ void attn_kernel(const float* __restrict__ qkv, float* __restrict__ out) {
    extern __shared__ float smf[];
    float* sQ = smf;
    float* sK = sQ + 64 * SQ_STR;
    float* sS = sK + 64 * SQ_STR;
    float* sV = sS + 64 * SQ_STR;
    float* sM = sV + 64 * SV_STR;
    float* sL = sM + 64;
    float* sA = sL + 64;

    int qb = blockIdx.x, h = blockIdx.y;
    int tid = threadIdx.x;
    int tx = tid & 15, ty = tid >> 4;

    for (int i = tid; i < 64 * 16; i += 256) {
        int r = i >> 4, c = (i & 15) << 2;
        float4 v = *(const float4*)(qkv + (size_t)(qb * 64 + r) * 1536 + h * 64 + c);
        float* q = sQ + r * SQ_STR + c;
        q[0] = v.x; q[1] = v.y; q[2] = v.z; q[3] = v.w;
    }
    if (tid < 64) { sM[tid] = -1e30f; sL[tid] = 0.f; }

    float acc[4][4];
    #pragma unroll
    for (int i = 0; i < 4; i++)
        #pragma unroll
        for (int j = 0; j < 4; j++) acc[i][j] = 0.f;

    for (int kb = 0; kb <= qb; kb++) {
        __syncthreads();
        for (int i = tid; i < 64 * 16; i += 256) {
            int r = i >> 4, c = (i & 15) << 2;
            const float* base = qkv + (size_t)(kb * 64 + r) * 1536 + h * 64 + c;
            float4 kv = *(const float4*)(base + 512);
            float4 vv = *(const float4*)(base + 1024);
            float* kd = sK + r * SQ_STR + c;
            kd[0] = kv.x; kd[1] = kv.y; kd[2] = kv.z; kd[3] = kv.w;
            float* vd = sV + r * SV_STR + c;
            vd[0] = vv.x; vd[1] = vv.y; vd[2] = vv.z; vd[3] = vv.w;
        }
        __syncthreads();

        float s[4][4];
        #pragma unroll
        for (int i = 0; i < 4; i++)
            #pragma unroll
            for (int j = 0; j < 4; j++) s[i][j] = 0.f;
        #pragma unroll 4
        for (int dd = 0; dd < 64; dd++) {
            float a[4], bq[4];
            #pragma unroll
            for (int i = 0; i < 4; i++) a[i]  = sQ[(ty * 4 + i) * SQ_STR + dd];
            #pragma unroll
            for (int j = 0; j < 4; j++) bq[j] = sK[(tx * 4 + j) * SQ_STR + dd];
            #pragma unroll
            for (int i = 0; i < 4; i++)
                #pragma unroll
                for (int j = 0; j < 4; j++)
                    s[i][j] = fmaf(a[i], bq[j], s[i][j]);
        }
        bool diag = (kb == qb);
        #pragma unroll
        for (int i = 0; i < 4; i++)
            #pragma unroll
            for (int j = 0; j < 4; j++) {
                float val = s[i][j] * 0.125f;
                if (diag && (tx * 4 + j) > (ty * 4 + i)) val = -1e30f;
                sS[(ty * 4 + i) * SQ_STR + tx * 4 + j] = val;
            }
        __syncthreads();

        if (tid < 64) {
            float m = sM[tid];
            float mn = m;
            float* srow = sS + tid * SQ_STR;
            #pragma unroll 8
            for (int j = 0; j < 64; j++) mn = fmaxf(mn, srow[j]);
            float alpha = __expf(m - mn);
            float lsum = sL[tid] * alpha;
            #pragma unroll 8
            for (int j = 0; j < 64; j++) {
                float p = __expf(srow[j] - mn);
                srow[j] = p;
                lsum += p;
            }
            sM[tid] = mn; sL[tid] = lsum; sA[tid] = alpha;
        }
        __syncthreads();

        float al4[4];
        #pragma unroll
        for (int i = 0; i < 4; i++) al4[i] = sA[ty * 4 + i];
        #pragma unroll
        for (int i = 0; i < 4; i++)
            #pragma unroll
            for (int j = 0; j < 4; j++) acc[i][j] *= al4[i];
        #pragma unroll 4
        for (int kk = 0; kk < 64; kk++) {
            float p[4];
            #pragma unroll
            for (int i = 0; i < 4; i++) p[i] = sS[(ty * 4 + i) * SQ_STR + kk];
            float4 vv = *(const float4*)(sV + kk * SV_STR + tx * 4);
            #pragma unroll
            for (int i = 0; i < 4; i++) {
                acc[i][0] = fmaf(p[i], vv.x, acc[i][0]);
                acc[i][1] = fmaf(p[i], vv.y, acc[i][1]);
                acc[i][2] = fmaf(p[i], vv.z, acc[i][2]);
                acc[i][3] = fmaf(p[i], vv.w, acc[i][3]);
            }
        }
    }

    float inv[4];
    #pragma unroll
    for (int i = 0; i < 4; i++) inv[i] = 1.f / sL[ty * 4 + i];
    #pragma unroll
    for (int i = 0; i < 4; i++) {
        float* op = out + (size_t)(qb * 64 + ty * 4 + i) * D_DIM + h * 64 + tx * 4;
        #pragma unroll
        for (int j = 0; j < 4; j++) op[j] = acc[i][j] * inv[i];
    }
}

// ---------------- launch ----------------
extern "C" void kernel_launch(void* const* d_in, const int* in_sizes, int n_in,
                              void* d_out, int out_size) {
    const float* x    = (const float*)d_in[0];
    const float* wqkv = (const float*)d_in[1];
    const float* bqkv = (const float*)d_in[2];
    const float* wout = (const float*)d_in[3];
    const float* bout = (const float*)d_in[4];
    const float* wff1 = (const float*)d_in[5];
    const float* bff1 = (const float*)d_in[6];
    const float* wff2 = (const float*)d_in[7];
    const float* bff2 = (const float*)d_in[8];
    const float* g1   = (const float*)d_in[9];
    const float* bt1  = (const float*)d_in[10];
    const float* g2   = (const float*)d_in[11];
    const float* bt2  = (const float*)d_in[12];
    float* out = (float*)d_out;

    float *ph, *pqkv, *pattn, *px1, *ph2, *pff;
    cudaGetSymbolAddress((void**)&ph,    g_h);
    cudaGetSymbolAddress((void**)&pqkv,  g_qkv);
    cudaGetSymbolAddress((void**)&pattn, g_attn);
    cudaGetSymbolAddress((void**)&px1,   g_x1);
    cudaGetSymbolAddress((void**)&ph2,   g_h2);
    cudaGetSymbolAddress((void**)&pff,   g_ff);

    int smem_attn = ATTN_SMEM_FLOATS * (int)sizeof(float);
    cudaFuncSetAttribute(attn_kernel, cudaFuncAttributeMaxDynamicSharedMemorySize, smem_attn);

    // 1) h = LN1(x)
    ln_kernel<<<S_LEN, 256>>>(x, g1, bt1, ph);
    // 2) qkv = h @ w_qkv + b_qkv   [4096 x 1536], K=512
    gemm_mma<128, 512, 0><<<dim3(12, 32), 256>>>(ph, wqkv, bqkv, nullptr, pqkv, 1536);
    // 3) attention
    attn_kernel<<<dim3(S_LEN / 64, H_NUM), 256, smem_attn>>>(pqkv, pattn);
    // 4) x1 = x + attn @ w_out + b_out  [4096 x 512], K=512
    gemm_mma<64, 512, 2><<<dim3(8, 32), 256>>>(pattn, wout, bout, x, px1, 512);
    // 5) h2 = LN2(x1)
    ln_kernel<<<S_LEN, 256>>>(px1, g2, bt2, ph2);
    // 6) ff = gelu(h2 @ w_ff1 + b_ff1)  [4096 x 1024], K=512
    gemm_mma<128, 512, 1><<<dim3(8, 32), 256>>>(ph2, wff1, bff1, nullptr, pff, 1024);
    // 7) out = x1 + ff @ w_ff2 + b_ff2  [4096 x 512], K=1024
    gemm_mma<64, 1024, 2><<<dim3(8, 32), 256>>>(pff, wff2, bff2, px1, out, 512);
}

// round 4
// speedup vs baseline: 2.2643x; 1.7246x over previous
#include <cuda_runtime.h>
#include <cuda_bf16.h>
#include <math.h>
#include <stdint.h>

#define S_LEN 4096
#define D_DIM 512
#define H_NUM 8
#define FF_DIM 1024
#define EPS_LN 1e-5f

// ---------------- scratch (no allocations allowed) ----------------
__device__ float g_h   [S_LEN * D_DIM];
__device__ float g_qkv [S_LEN * 3 * D_DIM];
__device__ float g_attn[S_LEN * D_DIM];
__device__ float g_x1  [S_LEN * D_DIM];
__device__ float g_h2  [S_LEN * D_DIM];
__device__ float g_ff  [S_LEN * FF_DIM];

__device__ __forceinline__ uint32_t smem_u32(const void* p) {
    uint32_t a;
    asm("{ .reg .u64 t; cvta.to.shared.u64 t, %1; cvt.u32.u64 %0, t; }" : "=r"(a) : "l"(p));
    return a;
}

#define LDMATRIX_X4(r0, r1, r2, r3, a) \
    asm volatile("ldmatrix.sync.aligned.m8n8.x4.shared.b16 {%0,%1,%2,%3}, [%4];" \
        : "=r"(r0), "=r"(r1), "=r"(r2), "=r"(r3) : "r"(a))
#define LDMATRIX_X2(r0, r1, a) \
    asm volatile("ldmatrix.sync.aligned.m8n8.x2.shared.b16 {%0,%1}, [%2];" \
        : "=r"(r0), "=r"(r1) : "r"(a))
#define MMA_BF16(d, a, b) \
    asm volatile("mma.sync.aligned.m16n8k16.row.col.f32.bf16.bf16.f32 " \
        "{%0,%1,%2,%3}, {%4,%5,%6,%7}, {%8,%9}, {%0,%1,%2,%3};" \
        : "+f"((d)[0]), "+f"((d)[1]), "+f"((d)[2]), "+f"((d)[3]) \
        : "r"((a)[0]), "r"((a)[1]), "r"((a)[2]), "r"((a)[3]), "r"((b)[0]), "r"((b)[1]))

__device__ __forceinline__ void split_bf16(float4 v, uint2& hp, uint2& lp) {
    __nv_bfloat162 h01 = __floats2bfloat162_rn(v.x, v.y);
    __nv_bfloat162 h23 = __floats2bfloat162_rn(v.z, v.w);
    float lx = v.x - __bfloat162float(__low2bfloat16(h01));
    float ly = v.y - __bfloat162float(__high2bfloat16(h01));
    float lz = v.z - __bfloat162float(__low2bfloat16(h23));
    float lw = v.w - __bfloat162float(__high2bfloat16(h23));
    __nv_bfloat162 l01 = __floats2bfloat162_rn(lx, ly);
    __nv_bfloat162 l23 = __floats2bfloat162_rn(lz, lw);
    hp.x = *(uint32_t*)&h01; hp.y = *(uint32_t*)&h23;
    lp.x = *(uint32_t*)&l01; lp.y = *(uint32_t*)&l23;
}
__device__ __forceinline__ uint32_t pack_bf16(float x, float y) {
    __nv_bfloat162 h = __floats2bfloat162_rn(x, y);
    return *(uint32_t*)&h;
}
__device__ __forceinline__ uint32_t pack_bf16_lo(float x, float y, uint32_t hp) {
    __nv_bfloat162 h = *(__nv_bfloat162*)&hp;
    float lx = x - __bfloat162float(__low2bfloat16(h));
    float ly = y - __bfloat162float(__high2bfloat16(h));
    __nv_bfloat162 lo = __floats2bfloat162_rn(lx, ly);
    return *(uint32_t*)&lo;
}

// ---------------- LayerNorm ----------------
__global__ void ln_kernel(const float* __restrict__ x, const float* __restrict__ g,
                          const float* __restrict__ b, float* __restrict__ out) {
    __shared__ float red[32];
    __shared__ float s_mean, s_rstd;
    int row = blockIdx.x;
    int tid = threadIdx.x;
    const float* xr = x + (size_t)row * D_DIM;
    float2 v = *(const float2*)(xr + tid * 2);

    float sum = v.x + v.y;
    #pragma unroll
    for (int o = 16; o > 0; o >>= 1) sum += __shfl_down_sync(0xffffffffu, sum, o);
    if ((tid & 31) == 0) red[tid >> 5] = sum;
    __syncthreads();
    if (tid < 32) {
        float t = (tid < 8) ? red[tid] : 0.f;
        #pragma unroll
        for (int o = 4; o > 0; o >>= 1) t += __shfl_down_sync(0xffffffffu, t, o);
        if (tid == 0) s_mean = t * (1.f / D_DIM);
    }
    __syncthreads();
    float mean = s_mean;
    float d0 = v.x - mean, d1 = v.y - mean;

    float vs = d0 * d0 + d1 * d1;
    #pragma unroll
    for (int o = 16; o > 0; o >>= 1) vs += __shfl_down_sync(0xffffffffu, vs, o);
    if ((tid & 31) == 0) red[tid >> 5] = vs;
    __syncthreads();
    if (tid < 32) {
        float t = (tid < 8) ? red[tid] : 0.f;
        #pragma unroll
        for (int o = 4; o > 0; o >>= 1) t += __shfl_down_sync(0xffffffffu, t, o);
        if (tid == 0) s_rstd = rsqrtf(t * (1.f / D_DIM) + EPS_LN);
    }
    __syncthreads();
    float rstd = s_rstd;

    int c = tid * 2;
    float2 gg = *(const float2*)(g + c);
    float2 bb = *(const float2*)(b + c);
    float2 o2;
    o2.x = d0 * rstd * gg.x + bb.x;
    o2.y = d1 * rstd * gg.y + bb.y;
    *(float2*)(out + (size_t)row * D_DIM + c) = o2;
}

// ---------------- mma.sync split-bf16 GEMM (register-prefetch pipelined) ----------------
template <int BN, int K_TOT, int EPI>
__global__ void __launch_bounds__(256, 2)
gemm_mma(const float* __restrict__ A, const float* __restrict__ B,
         const float* __restrict__ bias, const float* __restrict__ res,
         float* __restrict__ C, int N) {
    constexpr int WARPS_N = BN / 32;
    constexpr int WARPS_M = 8 / WARPS_N;
    constexpr int WM = 128 / WARPS_M;
    constexpr int MI = WM / 16;
    constexpr int A_BYTES = 128 * 80;
    constexpr int B_BYTES = BN * 80;
    constexpr int NS = K_TOT / 32;

    __shared__ __align__(16) char sm[2 * A_BYTES + 2 * B_BYTES];

    const uint32_t sbase = smem_u32(sm);
    const uint32_t sAh = sbase;
    const uint32_t sBh = sbase + 2 * A_BYTES;

    int tid = threadIdx.x;
    int wid = tid >> 5;
    int l = tid & 31;
    int bm = blockIdx.y * 128, bn = blockIdx.x * BN;
    int warp_m = wid / WARPS_N, warp_n = wid % WARPS_N;

    float d[MI][4][4];
    #pragma unroll
    for (int i = 0; i < MI; i++)
        #pragma unroll
        for (int j = 0; j < 4; j++)
            #pragma unroll
            for (int k = 0; k < 4; k++) d[i][j][k] = 0.f;

    int a_row = tid >> 1;
    int a_cb = (tid & 1) * 16;
    int b_nb = tid % (BN / 4);
    int b_kb = tid / (BN / 4);
    bool b_act = (BN == 128) || (tid < 128);

    int lb = l & 15;
    uint32_t a_lm = sAh + (uint32_t)(warp_m * WM + lb) * 80 + (uint32_t)(l >> 4) * 16;
    uint32_t b_lm = sBh + (uint32_t)(warp_n * 32 + (lb & 7)) * 80 + (uint32_t)(lb >> 3) * 16;

    float4 aR[4], bR[4];
    // preload slice 0
    {
        const float* ap = A + (size_t)(bm + a_row) * K_TOT + a_cb;
        #pragma unroll
        for (int i = 0; i < 4; i++) aR[i] = *(const float4*)(ap + i * 4);
        if (b_act) {
            const float* bp = B + (size_t)(b_kb * 4) * N + bn + b_nb * 4;
            #pragma unroll
            for (int i = 0; i < 4; i++) bR[i] = *(const float4*)(bp + (size_t)i * N);
        }
    }

    for (int s = 0; s < NS; s++) {
        // store current regs to smem (split)
        {
            uint32_t base = (uint32_t)(a_row * 80 + a_cb * 2);
            #pragma unroll
            for (int i = 0; i < 4; i++) {
                uint2 hp, lp;
                split_bf16(aR[i], hp, lp);
                *(uint2*)(sm + base + i * 8) = hp;
                *(uint2*)(sm + A_BYTES + base + i * 8) = lp;
            }
        }
        if (b_act) {
            float4 cols[4] = {
                {bR[0].x, bR[1].x, bR[2].x, bR[3].x},
                {bR[0].y, bR[1].y, bR[2].y, bR[3].y},
                {bR[0].z, bR[1].z, bR[2].z, bR[3].z},
                {bR[0].w, bR[1].w, bR[2].w, bR[3].w}};
            #pragma unroll
            for (int nn = 0; nn < 4; nn++) {
                uint2 hp, lp;
                split_bf16(cols[nn], hp, lp);
                uint32_t off = (uint32_t)((b_nb * 4 + nn) * 80 + b_kb * 8);
                *(uint2*)(sm + 2 * A_BYTES + off) = hp;
                *(uint2*)(sm + 2 * A_BYTES + B_BYTES + off) = lp;
            }
        }
        __syncthreads();

        // prefetch next slice while computing
        if (s + 1 < NS) {
            int k0 = (s + 1) * 32;
            const float* ap = A + (size_t)(bm + a_row) * K_TOT + k0 + a_cb;
            #pragma unroll
            for (int i = 0; i < 4; i++) aR[i] = *(const float4*)(ap + i * 4);
            if (b_act) {
                const float* bp = B + (size_t)(k0 + b_kb * 4) * N + bn + b_nb * 4;
                #pragma unroll
                for (int i = 0; i < 4; i++) bR[i] = *(const float4*)(bp + (size_t)i * N);
            }
        }

        #pragma unroll
        for (int ks = 0; ks < 2; ks++) {
            uint32_t bh[4][2], blo[4][2];
            #pragma unroll
            for (int nj = 0; nj < 4; nj++) {
                uint32_t ba = b_lm + nj * 8 * 80 + ks * 32;
                LDMATRIX_X2(bh[nj][0], bh[nj][1], ba);
                LDMATRIX_X2(blo[nj][0], blo[nj][1], ba + B_BYTES);
            }
            #pragma unroll
            for (int mi = 0; mi < MI; mi++) {
                uint32_t ah[4], al[4];
                uint32_t aa = a_lm + mi * 16 * 80 + ks * 32;
                LDMATRIX_X4(ah[0], ah[1], ah[2], ah[3], aa);
                LDMATRIX_X4(al[0], al[1], al[2], al[3], aa + A_BYTES);
                #pragma unroll
                for (int nj = 0; nj < 4; nj++) {
                    MMA_BF16(d[mi][nj], ah, bh[nj]);
                    MMA_BF16(d[mi][nj], ah, blo[nj]);
                    MMA_BF16(d[mi][nj], al, bh[nj]);
                }
            }
        }
        __syncthreads();
    }

    #pragma unroll
    for (int mi = 0; mi < MI; mi++) {
        int row0 = bm + warp_m * WM + mi * 16 + (l >> 2);
        #pragma unroll
        for (int nj = 0; nj < 4; nj++) {
            int col = bn + warp_n * 32 + nj * 8 + (l & 3) * 2;
            float2 bb = *(const float2*)(bias + col);
            #pragma unroll
            for (int half = 0; half < 2; half++) {
                int row = row0 + half * 8;
                float vx = d[mi][nj][half * 2 + 0] + bb.x;
                float vy = d[mi][nj][half * 2 + 1] + bb.y;
                if (EPI == 1) {
                    vx = 0.5f * vx * (1.f + erff(vx * 0.70710678118654752f));
                    vy = 0.5f * vy * (1.f + erff(vy * 0.70710678118654752f));
                }
                if (EPI == 2) {
                    float2 rr = *(const float2*)(res + (size_t)row * N + col);
                    vx += rr.x; vy += rr.y;
                }
                float2 o2; o2.x = vx; o2.y = vy;
                *(float2*)(C + (size_t)row * N + col) = o2;
            }
        }
    }
}

// ---------------- mma.sync flash attention ----------------
// 128 queries/block (8 warps x 16 rows), 64-key tiles, DH=64.
// QK^T: 3-pass split-bf16.  P@V: Ph*Vh + Ph*Vl + Pl*Vh.
#define ATT_STR 144
#define ATT_QH 0
#define ATT_QL (128 * ATT_STR)
#define ATT_KH (2 * 128 * ATT_STR)
#define ATT_KL (ATT_KH + 64 * ATT_STR)
#define ATT_VH (ATT_KH + 2 * 64 * ATT_STR)
#define ATT_VL (ATT_VH + 64 * ATT_STR)
#define ATT_SMEM (ATT_VH + 2 * 64 * ATT_STR)

__global__ void __launch_bounds__(256, 1)
attn_mma(const float* __restrict__ qkv, float* __restrict__ out) {
    extern __shared__ char sm[];
    const uint32_t sbase = smem_u32(sm);

    int qb = (int)gridDim.x - 1 - (int)blockIdx.x;   // heavy blocks first
    int h = blockIdx.y;
    int tid = threadIdx.x;
    int w = tid >> 5;
    int l = tid & 31;
    int lb = l & 15;

    // ---- load Q tile (128 x 64), split hi/lo ----
    {
        int row = tid >> 1;
        int colb = (tid & 1) * 32;
        const float* qp = qkv + (size_t)(qb * 128 + row) * 1536 + h * 64 + colb;
        uint32_t base = (uint32_t)(row * ATT_STR + colb * 2);
        #pragma unroll
        for (int i = 0; i < 8; i++) {
            float4 v = *(const float4*)(qp + i * 4);
            uint2 hp, lp;
            split_bf16(v, hp, lp);
            *(uint2*)(sm + ATT_QH + base + i * 8) = hp;
            *(uint2*)(sm + ATT_QL + base + i * 8) = lp;
        }
    }

    float o[8][4];
    #pragma unroll
    for (int j = 0; j < 8; j++)
        #pragma unroll
        for (int k = 0; k < 4; k++) o[j][k] = 0.f;
    float m0 = -1e30f, m1 = -1e30f, l0 = 0.f, l1 = 0.f;

    uint32_t aq = sbase + ATT_QH + (uint32_t)((16 * w + lb) * ATT_STR) + (uint32_t)(l >> 4) * 16;
    uint32_t bk = sbase + ATT_KH + (uint32_t)((lb & 7) * ATT_STR) + (uint32_t)(lb >> 3) * 16;
    uint32_t bv = sbase + ATT_VH + (uint32_t)((lb & 7) * ATT_STR) + (uint32_t)(lb >> 3) * 16;

    int row0g = qb * 128 + 16 * w + (l >> 2);
    int kb_max = 2 * qb + 1;

    for (int kb = 0; kb <= kb_max; kb++) {
        __syncthreads();
        // ---- load K tile (64 keys x 64) ----
        {
            int row = tid >> 2;
            int colb = (tid & 3) * 16;
            const float* kp = qkv + (size_t)(kb * 64 + row) * 1536 + 512 + h * 64 + colb;
            uint32_t base = (uint32_t)(row * ATT_STR + colb * 2);
            #pragma unroll
            for (int i = 0; i < 4; i++) {
                float4 v = *(const float4*)(kp + i * 4);
                uint2 hp, lp;
                split_bf16(v, hp, lp);
                *(uint2*)(sm + ATT_KH + base + i * 8) = hp;
                *(uint2*)(sm + ATT_KL + base + i * 8) = lp;
            }
        }
        // ---- load V tile transposed: sVt[dh][key] ----
        {
            int kb4 = (tid & 15) * 4;
            int db4 = (tid >> 4) * 4;
            const float* vp = qkv + (size_t)(kb * 64 + kb4) * 1536 + 1024 + h * 64 + db4;
            float4 r0 = *(const float4*)(vp);
            float4 r1 = *(const float4*)(vp + 1536);
            float4 r2 = *(const float4*)(vp + 3072);
            float4 r3 = *(const float4*)(vp + 4608);
            float4 cols[4] = {
                {r0.x, r1.x, r2.x, r3.x},
                {r0.y, r1.y, r2.y, r3.y},
                {r0.z, r1.z, r2.z, r3.z},
                {r0.w, r1.w, r2.w, r3.w}};
            #pragma unroll
            for (int dd = 0; dd < 4; dd++) {
                uint2 hp, lp;
                split_bf16(cols[dd], hp, lp);
                uint32_t off = (uint32_t)((db4 + dd) * ATT_STR + kb4 * 2);
                *(uint2*)(sm + ATT_VH + off) = hp;
                *(uint2*)(sm + ATT_VL + off) = lp;
            }
        }
        __syncthreads();

        // ---- S = Q K^T (3-pass split) ----
        float s[8][4];
        #pragma unroll
        for (int j = 0; j < 8; j++)
            #pragma unroll
            for (int k = 0; k < 4; k++) s[j][k] = 0.f;
        #pragma unroll
        for (int ks = 0; ks < 4; ks++) {
            uint32_t ah[4], al[4];
            LDMATRIX_X4(ah[0], ah[1], ah[2], ah[3], aq + ks * 32);
            LDMATRIX_X4(al[0], al[1], al[2], al[3], aq + ks * 32 + (ATT_QL - ATT_QH));
            #pragma unroll
            for (int j = 0; j < 8; j++) {
                uint32_t bh[2], blo[2];
                uint32_t ba = bk + j * 8 * ATT_STR + ks * 32;
                LDMATRIX_X2(bh[0], bh[1], ba);
                LDMATRIX_X2(blo[0], blo[1], ba + (ATT_KL - ATT_KH));
                MMA_BF16(s[j], ah, bh);
                MMA_BF16(s[j], ah, blo);
                MMA_BF16(s[j], al, bh);
            }
        }

        // ---- scale + causal mask ----
        int cbase = kb * 64 + 2 * (l & 3);
        bool need_mask = (kb >= 2 * qb);
        #pragma unroll
        for (int j = 0; j < 8; j++) {
            #pragma unroll
            for (int k = 0; k < 4; k++) s[j][k] *= 0.125f;
            if (need_mask) {
                int c0 = cbase + 8 * j;
                if (c0 > row0g)     s[j][0] = -1e30f;
                if (c0 + 1 > row0g) s[j][1] = -1e30f;
                if (c0 > row0g + 8)     s[j][2] = -1e30f;
                if (c0 + 1 > row0g + 8) s[j][3] = -1e30f;
            }
        }

        // ---- online softmax ----
        float mn0 = m0, mn1 = m1;
        #pragma unroll
        for (int j = 0; j < 8; j++) {
            mn0 = fmaxf(mn0, fmaxf(s[j][0], s[j][1]));
            mn1 = fmaxf(mn1, fmaxf(s[j][2], s[j][3]));
        }
        mn0 = fmaxf(mn0, __shfl_xor_sync(0xffffffffu, mn0, 1));
        mn0 = fmaxf(mn0, __shfl_xor_sync(0xffffffffu, mn0, 2));
        mn1 = fmaxf(mn1, __shfl_xor_sync(0xffffffffu, mn1, 1));
        mn1 = fmaxf(mn1, __shfl_xor_sync(0xffffffffu, mn1, 2));
        float alpha0 = __expf(m0 - mn0);
        float alpha1 = __expf(m1 - mn1);
        m0 = mn0; m1 = mn1;
        float rs0 = 0.f, rs1 = 0.f;
        #pragma unroll
        for (int j = 0; j < 8; j++) {
            s[j][0] = __expf(s[j][0] - mn0);
            s[j][1] = __expf(s[j][1] - mn0);
            s[j][2] = __expf(s[j][2] - mn1);
            s[j][3] = __expf(s[j][3] - mn1);
            rs0 += s[j][0] + s[j][1];
            rs1 += s[j][2] + s[j][3];
        }
        l0 = l0 * alpha0 + rs0;
        l1 = l1 * alpha1 + rs1;
        #pragma unroll
        for (int j = 0; j < 8; j++) {
            o[j][0] *= alpha0; o[j][1] *= alpha0;
            o[j][2] *= alpha1; o[j][3] *= alpha1;
        }

        // ---- O += P @ V ----
        #pragma unroll
        for (int ks = 0; ks < 4; ks++) {
            uint32_t pa[4], pl[4];
            pa[0] = pack_bf16(s[2 * ks][0], s[2 * ks][1]);
            pa[1] = pack_bf16(s[2 * ks][2], s[2 * ks][3]);
            pa[2] = pack_bf16(s[2 * ks + 1][0], s[2 * ks + 1][1]);
            pa[3] = pack_bf16(s[2 * ks + 1][2], s[2 * ks + 1][3]);
            pl[0] = pack_bf16_lo(s[2 * ks][0], s[2 * ks][1], pa[0]);
            pl[1] = pack_bf16_lo(s[2 * ks][2], s[2 * ks][3], pa[1]);
            pl[2] = pack_bf16_lo(s[2 * ks + 1][0], s[2 * ks + 1][1], pa[2]);
            pl[3] = pack_bf16_lo(s[2 * ks + 1][2], s[2 * ks + 1][3], pa[3]);
            #pragma unroll
            for (int j = 0; j < 8; j++) {
                uint32_t vh[2], vl[2];
                uint32_t va = bv + j * 8 * ATT_STR + ks * 32;
                LDMATRIX_X2(vh[0], vh[1], va);
                LDMATRIX_X2(vl[0], vl[1], va + (ATT_VL - ATT_VH));
                MMA_BF16(o[j], pa, vh);
                MMA_BF16(o[j], pa, vl);
                MMA_BF16(o[j], pl, vh);
            }
        }
    }

    // ---- finalize ----
    l0 += __shfl_xor_sync(0xffffffffu, l0, 1);
    l0 += __shfl_xor_sync(0xffffffffu, l0, 2);
    l1 += __shfl_xor_sync(0xffffffffu, l1, 1);
    l1 += __shfl_xor_sync(0xffffffffu, l1, 2);
    float inv0 = 1.f / l0, inv1 = 1.f / l1;
    #pragma unroll
    for (int j = 0; j < 8; j++) {
        int col = h * 64 + 8 * j + 2 * (l & 3);
        float2 o0; o0.x = o[j][0] * inv0; o0.y = o[j][1] * inv0;
        float2 o1; o1.x = o[j][2] * inv1; o1.y = o[j][3] * inv1;
        *(float2*)(out + (size_t)row0g * D_DIM + col) = o0;
        *(float2*)(out + (size_t)(row0g + 8) * D_DIM + col) = o1;
    }
}

// ---------------- launch ----------------
extern "C" void kernel_launch(void* const* d_in, const int* in_sizes, int n_in,
                              void* d_out, int out_size) {
    const float* x    = (const float*)d_in[0];
    const float* wqkv = (const float*)d_in[1];
    const float* bqkv = (const float*)d_in[2];
    const float* wout = (const float*)d_in[3];
    const float* bout = (const float*)d_in[4];
    const float* wff1 = (const float*)d_in[5];
    const float* bff1 = (const float*)d_in[6];
    const float* wff2 = (const float*)d_in[7];
    const float* bff2 = (const float*)d_in[8];
    const float* g1   = (const float*)d_in[9];
    const float* bt1  = (const float*)d_in[10];
    const float* g2   = (const float*)d_in[11];
    const float* bt2  = (const float*)d_in[12];
    float* out = (float*)d_out;

    float *ph, *pqkv, *pattn, *px1, *ph2, *pff;
    cudaGetSymbolAddress((void**)&ph,    g_h);
    cudaGetSymbolAddress((void**)&pqkv,  g_qkv);
    cudaGetSymbolAddress((void**)&pattn, g_attn);
    cudaGetSymbolAddress((void**)&px1,   g_x1);
    cudaGetSymbolAddress((void**)&ph2,   g_h2);
    cudaGetSymbolAddress((void**)&pff,   g_ff);

    cudaFuncSetAttribute(attn_mma, cudaFuncAttributeMaxDynamicSharedMemorySize, ATT_SMEM);

    // 1) h = LN1(x)
    ln_kernel<<<S_LEN, 256>>>(x, g1, bt1, ph);
    // 2) qkv = h @ w_qkv + b_qkv   [4096 x 1536], K=512
    gemm_mma<128, 512, 0><<<dim3(12, 32), 256>>>(ph, wqkv, bqkv, nullptr, pqkv, 1536);
    // 3) attention (tensor-core flash)
    attn_mma<<<dim3(S_LEN / 128, H_NUM), 256, ATT_SMEM>>>(pqkv, pattn);
    // 4) x1 = x + attn @ w_out + b_out  [4096 x 512], K=512
    gemm_mma<64, 512, 2><<<dim3(8, 32), 256>>>(pattn, wout, bout, x, px1, 512);
    // 5) h2 = LN2(x1)
    ln_kernel<<<S_LEN, 256>>>(px1, g2, bt2, ph2);
    // 6) ff = gelu(h2 @ w_ff1 + b_ff1)  [4096 x 1024], K=512
    gemm_mma<128, 512, 1><<<dim3(8, 32), 256>>>(ph2, wff1, bff1, nullptr, pff, 1024);
    // 7) out = x1 + ff @ w_ff2 + b_ff2  [4096 x 512], K=1024
    gemm_mma<64, 1024, 2><<<dim3(8, 32), 256>>>(pff, wff2, bff2, px1, out, 512);
}

// round 5
// speedup vs baseline: 2.2972x; 1.0145x over previous
#include <cuda_runtime.h>
#include <cuda_bf16.h>
#include <math.h>
#include <stdint.h>

#define S_LEN 4096
#define D_DIM 512
#define H_NUM 8
#define FF_DIM 1024
#define EPS_LN 1e-5f

// ---------------- scratch (no allocations allowed) ----------------
__device__ float g_h   [S_LEN * D_DIM];
__device__ float g_qkv [S_LEN * 3 * D_DIM];
__device__ float g_attn[S_LEN * D_DIM];
__device__ float g_x1  [S_LEN * D_DIM];
__device__ float g_h2  [S_LEN * D_DIM];
__device__ float g_ff  [S_LEN * FF_DIM];

__device__ __forceinline__ uint32_t smem_u32(const void* p) {
    uint32_t a;
    asm("{ .reg .u64 t; cvta.to.shared.u64 t, %1; cvt.u32.u64 %0, t; }" : "=r"(a) : "l"(p));
    return a;
}

#define LDMATRIX_X4(r0, r1, r2, r3, a) \
    asm volatile("ldmatrix.sync.aligned.m8n8.x4.shared.b16 {%0,%1,%2,%3}, [%4];" \
        : "=r"(r0), "=r"(r1), "=r"(r2), "=r"(r3) : "r"(a))
#define LDMATRIX_X2(r0, r1, a) \
    asm volatile("ldmatrix.sync.aligned.m8n8.x2.shared.b16 {%0,%1}, [%2];" \
        : "=r"(r0), "=r"(r1) : "r"(a))
#define MMA_BF16(d, a, b) \
    asm volatile("mma.sync.aligned.m16n8k16.row.col.f32.bf16.bf16.f32 " \
        "{%0,%1,%2,%3}, {%4,%5,%6,%7}, {%8,%9}, {%0,%1,%2,%3};" \
        : "+f"((d)[0]), "+f"((d)[1]), "+f"((d)[2]), "+f"((d)[3]) \
        : "r"((a)[0]), "r"((a)[1]), "r"((a)[2]), "r"((a)[3]), "r"((b)[0]), "r"((b)[1]))

__device__ __forceinline__ void split_bf16(float4 v, uint2& hp, uint2& lp) {
    __nv_bfloat162 h01 = __floats2bfloat162_rn(v.x, v.y);
    __nv_bfloat162 h23 = __floats2bfloat162_rn(v.z, v.w);
    float lx = v.x - __bfloat162float(__low2bfloat16(h01));
    float ly = v.y - __bfloat162float(__high2bfloat16(h01));
    float lz = v.z - __bfloat162float(__low2bfloat16(h23));
    float lw = v.w - __bfloat162float(__high2bfloat16(h23));
    __nv_bfloat162 l01 = __floats2bfloat162_rn(lx, ly);
    __nv_bfloat162 l23 = __floats2bfloat162_rn(lz, lw);
    hp.x = *(uint32_t*)&h01; hp.y = *(uint32_t*)&h23;
    lp.x = *(uint32_t*)&l01; lp.y = *(uint32_t*)&l23;
}
__device__ __forceinline__ uint32_t pack_bf16(float x, float y) {
    __nv_bfloat162 h = __floats2bfloat162_rn(x, y);
    return *(uint32_t*)&h;
}
__device__ __forceinline__ uint32_t pack_bf16_lo(float x, float y, uint32_t hp) {
    __nv_bfloat162 h = *(__nv_bfloat162*)&hp;
    float lx = x - __bfloat162float(__low2bfloat16(h));
    float ly = y - __bfloat162float(__high2bfloat16(h));
    __nv_bfloat162 lo = __floats2bfloat162_rn(lx, ly);
    return *(uint32_t*)&lo;
}

// ---------------- LayerNorm ----------------
__global__ void ln_kernel(const float* __restrict__ x, const float* __restrict__ g,
                          const float* __restrict__ b, float* __restrict__ out) {
    __shared__ float red[32];
    __shared__ float s_mean, s_rstd;
    int row = blockIdx.x;
    int tid = threadIdx.x;
    const float* xr = x + (size_t)row * D_DIM;
    float2 v = *(const float2*)(xr + tid * 2);

    float sum = v.x + v.y;
    #pragma unroll
    for (int o = 16; o > 0; o >>= 1) sum += __shfl_down_sync(0xffffffffu, sum, o);
    if ((tid & 31) == 0) red[tid >> 5] = sum;
    __syncthreads();
    if (tid < 32) {
        float t = (tid < 8) ? red[tid] : 0.f;
        #pragma unroll
        for (int o = 4; o > 0; o >>= 1) t += __shfl_down_sync(0xffffffffu, t, o);
        if (tid == 0) s_mean = t * (1.f / D_DIM);
    }
    __syncthreads();
    float mean = s_mean;
    float d0 = v.x - mean, d1 = v.y - mean;

    float vs = d0 * d0 + d1 * d1;
    #pragma unroll
    for (int o = 16; o > 0; o >>= 1) vs += __shfl_down_sync(0xffffffffu, vs, o);
    if ((tid & 31) == 0) red[tid >> 5] = vs;
    __syncthreads();
    if (tid < 32) {
        float t = (tid < 8) ? red[tid] : 0.f;
        #pragma unroll
        for (int o = 4; o > 0; o >>= 1) t += __shfl_down_sync(0xffffffffu, t, o);
        if (tid == 0) s_rstd = rsqrtf(t * (1.f / D_DIM) + EPS_LN);
    }
    __syncthreads();
    float rstd = s_rstd;

    int c = tid * 2;
    float2 gg = *(const float2*)(g + c);
    float2 bb = *(const float2*)(b + c);
    float2 o2;
    o2.x = d0 * rstd * gg.x + bb.x;
    o2.y = d1 * rstd * gg.y + bb.y;
    *(float2*)(out + (size_t)row * D_DIM + c) = o2;
}

// ---------------- mma.sync split-bf16 GEMM (double-buffered smem, 1 sync/slice) ----------------
template <int BN, int K_TOT, int EPI>
__global__ void __launch_bounds__(256, 2)
gemm_mma(const float* __restrict__ A, const float* __restrict__ B,
         const float* __restrict__ bias, const float* __restrict__ res,
         float* __restrict__ C, int N) {
    constexpr int WARPS_N = BN / 32;
    constexpr int WARPS_M = 8 / WARPS_N;
    constexpr int WM = 128 / WARPS_M;
    constexpr int MI = WM / 16;
    constexpr int NJ2 = 2;                      // 4 n-frags as 2 x4-pairs
    constexpr int A_BYTES = 128 * 80;
    constexpr int B_BYTES = BN * 80;
    constexpr int BUF = 2 * A_BYTES + 2 * B_BYTES;
    constexpr int NS = K_TOT / 32;

    extern __shared__ __align__(16) char smx[];
    const uint32_t sbase = smem_u32(smx);

    int tid = threadIdx.x;
    int wid = tid >> 5;
    int l = tid & 31;
    int bm = blockIdx.y * 128, bn = blockIdx.x * BN;
    int warp_m = wid / WARPS_N, warp_n = wid % WARPS_N;

    float d[MI][4][4];
    #pragma unroll
    for (int i = 0; i < MI; i++)
        #pragma unroll
        for (int j = 0; j < 4; j++)
            #pragma unroll
            for (int k = 0; k < 4; k++) d[i][j][k] = 0.f;

    int a_row = tid >> 1;
    int a_cb = (tid & 1) * 16;
    int b_nb = tid % (BN / 4);
    int b_kb = tid / (BN / 4);
    bool b_act = (BN == 128) || (tid < 128);

    int lb = l & 15;
    // A: x4 over 16 rows
    uint32_t a_lm = sbase + (uint32_t)(warp_m * WM + lb) * 80 + (uint32_t)(l >> 4) * 16;
    // B: x4 over two n-blocks: rows (pair*16 + (l>>4)*8 + (l&7)), k-half (l>>3)&1
    uint32_t b_lm = sbase + 2 * A_BYTES +
                    (uint32_t)(warp_n * 32 + (l >> 4) * 8 + (l & 7)) * 80 +
                    (uint32_t)((l >> 3) & 1) * 16;

    float4 aR[4], bR[4];
    {
        const float* ap = A + (size_t)(bm + a_row) * K_TOT + a_cb;
        #pragma unroll
        for (int i = 0; i < 4; i++) aR[i] = *(const float4*)(ap + i * 4);
        if (b_act) {
            const float* bp = B + (size_t)(b_kb * 4) * N + bn + b_nb * 4;
            #pragma unroll
            for (int i = 0; i < 4; i++) bR[i] = *(const float4*)(bp + (size_t)i * N);
        }
    }
    // store slice 0 into buf0
    {
        uint32_t base = (uint32_t)(a_row * 80 + a_cb * 2);
        #pragma unroll
        for (int i = 0; i < 4; i++) {
            uint2 hp, lp;
            split_bf16(aR[i], hp, lp);
            *(uint2*)(smx + base + i * 8) = hp;
            *(uint2*)(smx + A_BYTES + base + i * 8) = lp;
        }
        if (b_act) {
            float4 cols[4] = {
                {bR[0].x, bR[1].x, bR[2].x, bR[3].x},
                {bR[0].y, bR[1].y, bR[2].y, bR[3].y},
                {bR[0].z, bR[1].z, bR[2].z, bR[3].z},
                {bR[0].w, bR[1].w, bR[2].w, bR[3].w}};
            #pragma unroll
            for (int nn = 0; nn < 4; nn++) {
                uint2 hp, lp;
                split_bf16(cols[nn], hp, lp);
                uint32_t off = (uint32_t)((b_nb * 4 + nn) * 80 + b_kb * 8);
                *(uint2*)(smx + 2 * A_BYTES + off) = hp;
                *(uint2*)(smx + 2 * A_BYTES + B_BYTES + off) = lp;
            }
        }
    }
    __syncthreads();

    for (int s = 0; s < NS; s++) {
        // prefetch next slice into regs (overlaps with compute below)
        if (s + 1 < NS) {
            int k0 = (s + 1) * 32;
            const float* ap = A + (size_t)(bm + a_row) * K_TOT + k0 + a_cb;
            #pragma unroll
            for (int i = 0; i < 4; i++) aR[i] = *(const float4*)(ap + i * 4);
            if (b_act) {
                const float* bp = B + (size_t)(k0 + b_kb * 4) * N + bn + b_nb * 4;
                #pragma unroll
                for (int i = 0; i < 4; i++) bR[i] = *(const float4*)(bp + (size_t)i * N);
            }
        }

        uint32_t cb = (uint32_t)((s & 1) * BUF);
        #pragma unroll
        for (int ks = 0; ks < 2; ks++) {
            uint32_t bh[4][2], blo[4][2];
            #pragma unroll
            for (int pj = 0; pj < NJ2; pj++) {
                uint32_t ba = b_lm + cb + pj * 16 * 80 + ks * 32;
                LDMATRIX_X4(bh[2 * pj][0], bh[2 * pj][1], bh[2 * pj + 1][0], bh[2 * pj + 1][1], ba);
                LDMATRIX_X4(blo[2 * pj][0], blo[2 * pj][1], blo[2 * pj + 1][0], blo[2 * pj + 1][1], ba + B_BYTES);
            }
            #pragma unroll
            for (int mi = 0; mi < MI; mi++) {
                uint32_t ah[4], al[4];
                uint32_t aa = a_lm + cb + mi * 16 * 80 + ks * 32;
                LDMATRIX_X4(ah[0], ah[1], ah[2], ah[3], aa);
                LDMATRIX_X4(al[0], al[1], al[2], al[3], aa + A_BYTES);
                #pragma unroll
                for (int nj = 0; nj < 4; nj++) {
                    MMA_BF16(d[mi][nj], ah, bh[nj]);
                    MMA_BF16(d[mi][nj], ah, blo[nj]);
                    MMA_BF16(d[mi][nj], al, bh[nj]);
                }
            }
        }

        // store next slice into the other buffer; one sync per slice
        if (s + 1 < NS) {
            char* nb = smx + ((s + 1) & 1) * BUF;
            uint32_t base = (uint32_t)(a_row * 80 + a_cb * 2);
            #pragma unroll
            for (int i = 0; i < 4; i++) {
                uint2 hp, lp;
                split_bf16(aR[i], hp, lp);
                *(uint2*)(nb + base + i * 8) = hp;
                *(uint2*)(nb + A_BYTES + base + i * 8) = lp;
            }
            if (b_act) {
                float4 cols[4] = {
                    {bR[0].x, bR[1].x, bR[2].x, bR[3].x},
                    {bR[0].y, bR[1].y, bR[2].y, bR[3].y},
                    {bR[0].z, bR[1].z, bR[2].z, bR[3].z},
                    {bR[0].w, bR[1].w, bR[2].w, bR[3].w}};
                #pragma unroll
                for (int nn = 0; nn < 4; nn++) {
                    uint2 hp, lp;
                    split_bf16(cols[nn], hp, lp);
                    uint32_t off = (uint32_t)((b_nb * 4 + nn) * 80 + b_kb * 8);
                    *(uint2*)(nb + 2 * A_BYTES + off) = hp;
                    *(uint2*)(nb + 2 * A_BYTES + B_BYTES + off) = lp;
                }
            }
            __syncthreads();
        }
    }

    #pragma unroll
    for (int mi = 0; mi < MI; mi++) {
        int row0 = bm + warp_m * WM + mi * 16 + (l >> 2);
        #pragma unroll
        for (int nj = 0; nj < 4; nj++) {
            int col = bn + warp_n * 32 + nj * 8 + (l & 3) * 2;
            float2 bb = *(const float2*)(bias + col);
            #pragma unroll
            for (int half = 0; half < 2; half++) {
                int row = row0 + half * 8;
                float vx = d[mi][nj][half * 2 + 0] + bb.x;
                float vy = d[mi][nj][half * 2 + 1] + bb.y;
                if (EPI == 1) {
                    vx = 0.5f * vx * (1.f + erff(vx * 0.70710678118654752f));
                    vy = 0.5f * vy * (1.f + erff(vy * 0.70710678118654752f));
                }
                if (EPI == 2) {
                    float2 rr = *(const float2*)(res + (size_t)row * N + col);
                    vx += rr.x; vy += rr.y;
                }
                float2 o2; o2.x = vx; o2.y = vy;
                *(float2*)(C + (size_t)row * N + col) = o2;
            }
        }
    }
}

// ---------------- mma.sync flash attention (2 CTAs/SM) ----------------
#define ATT_STR 144
#define ATT_QH 0
#define ATT_QL (128 * ATT_STR)
#define ATT_KH (2 * 128 * ATT_STR)
#define ATT_KL (ATT_KH + 64 * ATT_STR)
#define ATT_VH (ATT_KH + 2 * 64 * ATT_STR)
#define ATT_VL (ATT_VH + 64 * ATT_STR)
#define ATT_SMEM (ATT_VH + 2 * 64 * ATT_STR)

__global__ void __launch_bounds__(256, 2)
attn_mma(const float* __restrict__ qkv, float* __restrict__ out) {
    extern __shared__ char sm[];
    const uint32_t sbase = smem_u32(sm);

    int qb = (int)gridDim.x - 1 - (int)blockIdx.x;   // heavy blocks first
    int h = blockIdx.y;
    int tid = threadIdx.x;
    int w = tid >> 5;
    int l = tid & 31;
    int lb = l & 15;

    // ---- load Q tile (128 x 64), split hi/lo ----
    {
        int row = tid >> 1;
        int colb = (tid & 1) * 32;
        const float* qp = qkv + (size_t)(qb * 128 + row) * 1536 + h * 64 + colb;
        uint32_t base = (uint32_t)(row * ATT_STR + colb * 2);
        #pragma unroll
        for (int i = 0; i < 8; i++) {
            float4 v = *(const float4*)(qp + i * 4);
            uint2 hp, lp;
            split_bf16(v, hp, lp);
            *(uint2*)(sm + ATT_QH + base + i * 8) = hp;
            *(uint2*)(sm + ATT_QL + base + i * 8) = lp;
        }
    }

    float o[8][4];
    #pragma unroll
    for (int j = 0; j < 8; j++)
        #pragma unroll
        for (int k = 0; k < 4; k++) o[j][k] = 0.f;
    float m0 = -1e30f, m1 = -1e30f, l0 = 0.f, l1 = 0.f;

    uint32_t aq = sbase + ATT_QH + (uint32_t)((16 * w + lb) * ATT_STR) + (uint32_t)(l >> 4) * 16;
    // x4 B-operand addresses spanning two 8-row n-blocks
    uint32_t bk = sbase + ATT_KH + (uint32_t)(((l >> 4) * 8 + (l & 7)) * ATT_STR) + (uint32_t)((l >> 3) & 1) * 16;
    uint32_t bv = sbase + ATT_VH + (uint32_t)(((l >> 4) * 8 + (l & 7)) * ATT_STR) + (uint32_t)((l >> 3) & 1) * 16;

    int row0g = qb * 128 + 16 * w + (l >> 2);
    int kb_max = 2 * qb + 1;

    for (int kb = 0; kb <= kb_max; kb++) {
        __syncthreads();
        // ---- load K tile (64 keys x 64) ----
        {
            int row = tid >> 2;
            int colb = (tid & 3) * 16;
            const float* kp = qkv + (size_t)(kb * 64 + row) * 1536 + 512 + h * 64 + colb;
            uint32_t base = (uint32_t)(row * ATT_STR + colb * 2);
            #pragma unroll
            for (int i = 0; i < 4; i++) {
                float4 v = *(const float4*)(kp + i * 4);
                uint2 hp, lp;
                split_bf16(v, hp, lp);
                *(uint2*)(sm + ATT_KH + base + i * 8) = hp;
                *(uint2*)(sm + ATT_KL + base + i * 8) = lp;
            }
        }
        // ---- load V tile transposed: sVt[dh][key] ----
        {
            int kb4 = (tid & 15) * 4;
            int db4 = (tid >> 4) * 4;
            const float* vp = qkv + (size_t)(kb * 64 + kb4) * 1536 + 1024 + h * 64 + db4;
            float4 r0 = *(const float4*)(vp);
            float4 r1 = *(const float4*)(vp + 1536);
            float4 r2 = *(const float4*)(vp + 3072);
            float4 r3 = *(const float4*)(vp + 4608);
            float4 cols[4] = {
                {r0.x, r1.x, r2.x, r3.x},
                {r0.y, r1.y, r2.y, r3.y},
                {r0.z, r1.z, r2.z, r3.z},
                {r0.w, r1.w, r2.w, r3.w}};
            #pragma unroll
            for (int dd = 0; dd < 4; dd++) {
                uint2 hp, lp;
                split_bf16(cols[dd], hp, lp);
                uint32_t off = (uint32_t)((db4 + dd) * ATT_STR + kb4 * 2);
                *(uint2*)(sm + ATT_VH + off) = hp;
                *(uint2*)(sm + ATT_VL + off) = lp;
            }
        }
        __syncthreads();

        // ---- S = Q K^T (3-pass split) ----
        float s[8][4];
        #pragma unroll
        for (int j = 0; j < 8; j++)
            #pragma unroll
            for (int k = 0; k < 4; k++) s[j][k] = 0.f;
        #pragma unroll
        for (int ks = 0; ks < 4; ks++) {
            uint32_t ah[4], al[4];
            LDMATRIX_X4(ah[0], ah[1], ah[2], ah[3], aq + ks * 32);
            LDMATRIX_X4(al[0], al[1], al[2], al[3], aq + ks * 32 + (ATT_QL - ATT_QH));
            #pragma unroll
            for (int jp = 0; jp < 4; jp++) {
                uint32_t bh[2][2], blo[2][2];
                uint32_t ba = bk + jp * 16 * ATT_STR + ks * 32;
                LDMATRIX_X4(bh[0][0], bh[0][1], bh[1][0], bh[1][1], ba);
                LDMATRIX_X4(blo[0][0], blo[0][1], blo[1][0], blo[1][1], ba + (ATT_KL - ATT_KH));
                #pragma unroll
                for (int q = 0; q < 2; q++) {
                    int j = 2 * jp + q;
                    MMA_BF16(s[j], ah, bh[q]);
                    MMA_BF16(s[j], ah, blo[q]);
                    MMA_BF16(s[j], al, bh[q]);
                }
            }
        }

        // ---- scale + causal mask ----
        int cbase = kb * 64 + 2 * (l & 3);
        bool need_mask = (kb >= 2 * qb);
        #pragma unroll
        for (int j = 0; j < 8; j++) {
            #pragma unroll
            for (int k = 0; k < 4; k++) s[j][k] *= 0.125f;
            if (need_mask) {
                int c0 = cbase + 8 * j;
                if (c0 > row0g)     s[j][0] = -1e30f;
                if (c0 + 1 > row0g) s[j][1] = -1e30f;
                if (c0 > row0g + 8)     s[j][2] = -1e30f;
                if (c0 + 1 > row0g + 8) s[j][3] = -1e30f;
            }
        }

        // ---- online softmax ----
        float mn0 = m0, mn1 = m1;
        #pragma unroll
        for (int j = 0; j < 8; j++) {
            mn0 = fmaxf(mn0, fmaxf(s[j][0], s[j][1]));
            mn1 = fmaxf(mn1, fmaxf(s[j][2], s[j][3]));
        }
        mn0 = fmaxf(mn0, __shfl_xor_sync(0xffffffffu, mn0, 1));
        mn0 = fmaxf(mn0, __shfl_xor_sync(0xffffffffu, mn0, 2));
        mn1 = fmaxf(mn1, __shfl_xor_sync(0xffffffffu, mn1, 1));
        mn1 = fmaxf(mn1, __shfl_xor_sync(0xffffffffu, mn1, 2));
        float alpha0 = __expf(m0 - mn0);
        float alpha1 = __expf(m1 - mn1);
        m0 = mn0; m1 = mn1;
        float rs0 = 0.f, rs1 = 0.f;
        #pragma unroll
        for (int j = 0; j < 8; j++) {
            s[j][0] = __expf(s[j][0] - mn0);
            s[j][1] = __expf(s[j][1] - mn0);
            s[j][2] = __expf(s[j][2] - mn1);
            s[j][3] = __expf(s[j][3] - mn1);
            rs0 += s[j][0] + s[j][1];
            rs1 += s[j][2] + s[j][3];
        }
        l0 = l0 * alpha0 + rs0;
        l1 = l1 * alpha1 + rs1;
        #pragma unroll
        for (int j = 0; j < 8; j++) {
            o[j][0] *= alpha0; o[j][1] *= alpha0;
            o[j][2] *= alpha1; o[j][3] *= alpha1;
        }

        // ---- O += P @ V ----
        #pragma unroll
        for (int ks = 0; ks < 4; ks++) {
            uint32_t pa[4], pl[4];
            pa[0] = pack_bf16(s[2 * ks][0], s[2 * ks][1]);
            pa[1] = pack_bf16(s[2 * ks][2], s[2 * ks][3]);
            pa[2] = pack_bf16(s[2 * ks + 1][0], s[2 * ks + 1][1]);
            pa[3] = pack_bf16(s[2 * ks + 1][2], s[2 * ks + 1][3]);
            pl[0] = pack_bf16_lo(s[2 * ks][0], s[2 * ks][1], pa[0]);
            pl[1] = pack_bf16_lo(s[2 * ks][2], s[2 * ks][3], pa[1]);
            pl[2] = pack_bf16_lo(s[2 * ks + 1][0], s[2 * ks + 1][1], pa[2]);
            pl[3] = pack_bf16_lo(s[2 * ks + 1][2], s[2 * ks + 1][3], pa[3]);
            #pragma unroll
            for (int jp = 0; jp < 4; jp++) {
                uint32_t vh[2][2], vl[2][2];
                uint32_t va = bv + jp * 16 * ATT_STR + ks * 32;
                LDMATRIX_X4(vh[0][0], vh[0][1], vh[1][0], vh[1][1], va);
                LDMATRIX_X4(vl[0][0], vl[0][1], vl[1][0], vl[1][1], va + (ATT_VL - ATT_VH));
                #pragma unroll
                for (int q = 0; q < 2; q++) {
                    int j = 2 * jp + q;
                    MMA_BF16(o[j], pa, vh[q]);
                    MMA_BF16(o[j], pa, vl[q]);
                    MMA_BF16(o[j], pl, vh[q]);
                }
            }
        }
    }

    // ---- finalize ----
    l0 += __shfl_xor_sync(0xffffffffu, l0, 1);
    l0 += __shfl_xor_sync(0xffffffffu, l0, 2);
    l1 += __shfl_xor_sync(0xffffffffu, l1, 1);
    l1 += __shfl_xor_sync(0xffffffffu, l1, 2);
    float inv0 = 1.f / l0, inv1 = 1.f / l1;
    #pragma unroll
    for (int j = 0; j < 8; j++) {
        int col = h * 64 + 8 * j + 2 * (l & 3);
        float2 o0; o0.x = o[j][0] * inv0; o0.y = o[j][1] * inv0;
        float2 o1; o1.x = o[j][2] * inv1; o1.y = o[j][3] * inv1;
        *(float2*)(out + (size_t)row0g * D_DIM + col) = o0;
        *(float2*)(out + (size_t)(row0g + 8) * D_DIM + col) = o1;
    }
}

// ---------------- launch ----------------
extern "C" void kernel_launch(void* const* d_in, const int* in_sizes, int n_in,
                              void* d_out, int out_size) {
    const float* x    = (const float*)d_in[0];
    const float* wqkv = (const float*)d_in[1];
    const float* bqkv = (const float*)d_in[2];
    const float* wout = (const float*)d_in[3];
    const float* bout = (const float*)d_in[4];
    const float* wff1 = (const float*)d_in[5];
    const float* bff1 = (const float*)d_in[6];
    const float* wff2 = (const float*)d_in[7];
    const float* bff2 = (const float*)d_in[8];
    const float* g1   = (const float*)d_in[9];
    const float* bt1  = (const float*)d_in[10];
    const float* g2   = (const float*)d_in[11];
    const float* bt2  = (const float*)d_in[12];
    float* out = (float*)d_out;

    float *ph, *pqkv, *pattn, *px1, *ph2, *pff;
    cudaGetSymbolAddress((void**)&ph,    g_h);
    cudaGetSymbolAddress((void**)&pqkv,  g_qkv);
    cudaGetSymbolAddress((void**)&pattn, g_attn);
    cudaGetSymbolAddress((void**)&px1,   g_x1);
    cudaGetSymbolAddress((void**)&ph2,   g_h2);
    cudaGetSymbolAddress((void**)&pff,   g_ff);

    const int GS128 = 2 * (2 * 128 * 80 + 2 * 128 * 80);  // 81920
    const int GS64  = 2 * (2 * 128 * 80 + 2 * 64 * 80);   // 61440
    cudaFuncSetAttribute(gemm_mma<128, 512, 0>, cudaFuncAttributeMaxDynamicSharedMemorySize, GS128);
    cudaFuncSetAttribute(gemm_mma<128, 512, 1>, cudaFuncAttributeMaxDynamicSharedMemorySize, GS128);
    cudaFuncSetAttribute(gemm_mma<64, 512, 2>,  cudaFuncAttributeMaxDynamicSharedMemorySize, GS64);
    cudaFuncSetAttribute(gemm_mma<64, 1024, 2>, cudaFuncAttributeMaxDynamicSharedMemorySize, GS64);
    cudaFuncSetAttribute(attn_mma, cudaFuncAttributeMaxDynamicSharedMemorySize, ATT_SMEM);

    // 1) h = LN1(x)
    ln_kernel<<<S_LEN, 256>>>(x, g1, bt1, ph);
    // 2) qkv = h @ w_qkv + b_qkv   [4096 x 1536], K=512
    gemm_mma<128, 512, 0><<<dim3(12, 32), 256, GS128>>>(ph, wqkv, bqkv, nullptr, pqkv, 1536);
    // 3) attention (tensor-core flash)
    attn_mma<<<dim3(S_LEN / 128, H_NUM), 256, ATT_SMEM>>>(pqkv, pattn);
    // 4) x1 = x + attn @ w_out + b_out  [4096 x 512], K=512
    gemm_mma<64, 512, 2><<<dim3(8, 32), 256, GS64>>>(pattn, wout, bout, x, px1, 512);
    // 5) h2 = LN2(x1)
    ln_kernel<<<S_LEN, 256>>>(px1, g2, bt2, ph2);
    // 6) ff = gelu(h2 @ w_ff1 + b_ff1)  [4096 x 1024], K=512
    gemm_mma<128, 512, 1><<<dim3(8, 32), 256, GS128>>>(ph2, wff1, bff1, nullptr, pff, 1024);
    // 7) out = x1 + ff @ w_ff2 + b_ff2  [4096 x 512], K=1024
    gemm_mma<64, 1024, 2><<<dim3(8, 32), 256, GS64>>>(pff, wff2, bff2, px1, out, 512);
}

// round 7
// speedup vs baseline: 2.6753x; 1.1646x over previous
#include <cuda_runtime.h>
#include <cuda_bf16.h>
#include <math.h>
#include <stdint.h>

typedef __nv_bfloat16 bf16;

#define S_LEN 4096
#define D_DIM 512
#define FF_DIM 1024
#define EPS_LN 1e-5f

// ---------------- persistent scratch (no allocations) ----------------
__device__ bf16 g_h_hi [S_LEN * D_DIM],  g_h_lo [S_LEN * D_DIM];
__device__ bf16 g_wqkvT_hi[1536 * 512],  g_wqkvT_lo[1536 * 512];
__device__ bf16 g_woutT_hi[512 * 512],   g_woutT_lo[512 * 512];
__device__ bf16 g_wff1T_hi[1024 * 512],  g_wff1T_lo[1024 * 512];
__device__ bf16 g_wff2T_hi[512 * 1024],  g_wff2T_lo[512 * 1024];
__device__ bf16 g_qk_hi[S_LEN * 1024],   g_qk_lo[S_LEN * 1024];
__device__ bf16 g_vt_hi[512 * S_LEN],    g_vt_lo[512 * S_LEN];   // [h*64+dh][seq]
__device__ bf16 g_ao_hi[S_LEN * D_DIM],  g_ao_lo[S_LEN * D_DIM];
__device__ bf16 g_h2_hi[S_LEN * D_DIM],  g_h2_lo[S_LEN * D_DIM];
__device__ bf16 g_ff_hi[S_LEN * FF_DIM], g_ff_lo[S_LEN * FF_DIM];
__device__ float g_x1[S_LEN * D_DIM];

__device__ __forceinline__ uint32_t smem_u32(const void* p) {
    uint32_t a;
    asm("{ .reg .u64 t; cvta.to.shared.u64 t, %1; cvt.u32.u64 %0, t; }" : "=r"(a) : "l"(p));
    return a;
}

#define LDMATRIX_X4(r0, r1, r2, r3, a) \
    asm volatile("ldmatrix.sync.aligned.m8n8.x4.shared.b16 {%0,%1,%2,%3}, [%4];" \
        : "=r"(r0), "=r"(r1), "=r"(r2), "=r"(r3) : "r"(a))
#define MMA_BF16(d, a, b) \
    asm volatile("mma.sync.aligned.m16n8k16.row.col.f32.bf16.bf16.f32 " \
        "{%0,%1,%2,%3}, {%4,%5,%6,%7}, {%8,%9}, {%0,%1,%2,%3};" \
        : "+f"((d)[0]), "+f"((d)[1]), "+f"((d)[2]), "+f"((d)[3]) \
        : "r"((a)[0]), "r"((a)[1]), "r"((a)[2]), "r"((a)[3]), "r"((b)[0]), "r"((b)[1]))

#define CP16(dst, src) asm volatile("cp.async.cg.shared.global [%0], [%1], 16;" :: "r"(dst), "l"(src))
#define CP_COMMIT()    asm volatile("cp.async.commit_group;")
#define CP_WAIT1()     asm volatile("cp.async.wait_group 1;" ::: "memory")
#define CP_WAIT0()     asm volatile("cp.async.wait_group 0;" ::: "memory")

__device__ __forceinline__ void split2(float x, float y, uint32_t& hp, uint32_t& lp) {
    __nv_bfloat162 h = __floats2bfloat162_rn(x, y);
    float lx = x - __bfloat162float(__low2bfloat16(h));
    float ly = y - __bfloat162float(__high2bfloat16(h));
    __nv_bfloat162 l = __floats2bfloat162_rn(lx, ly);
    hp = *(uint32_t*)&h; lp = *(uint32_t*)&l;
}
__device__ __forceinline__ uint32_t pack_bf16(float x, float y) {
    __nv_bfloat162 h = __floats2bfloat162_rn(x, y);
    return *(uint32_t*)&h;
}
__device__ __forceinline__ uint32_t pack_bf16_lo(float x, float y, uint32_t hp) {
    __nv_bfloat162 h = *(__nv_bfloat162*)&hp;
    float lx = x - __bfloat162float(__low2bfloat16(h));
    float ly = y - __bfloat162float(__high2bfloat16(h));
    __nv_bfloat162 lo = __floats2bfloat162_rn(lx, ly);
    return *(uint32_t*)&lo;
}

// ---------------- weight prep: [K][N] fp32 -> [N][K] split bf16 ----------------
__global__ void wprep(const float* __restrict__ src, bf16* __restrict__ dh,
                      bf16* __restrict__ dl, int K, int N) {
    __shared__ float t[32][33];
    int k0 = blockIdx.y * 32, n0 = blockIdx.x * 32;
    int tx = threadIdx.x & 31, ty = threadIdx.x >> 5;
    #pragma unroll
    for (int i = 0; i < 32; i += 8)
        t[ty + i][tx] = src[(size_t)(k0 + ty + i) * N + n0 + tx];
    __syncthreads();
    #pragma unroll
    for (int i = 0; i < 32; i += 8) {
        float v = t[tx][ty + i];
        bf16 h = __float2bfloat16(v);
        bf16 l = __float2bfloat16(v - __bfloat162float(h));
        size_t idx = (size_t)(n0 + ty + i) * K + k0 + tx;
        dh[idx] = h; dl[idx] = l;
    }
}

// ---------------- LayerNorm -> split bf16 ----------------
__global__ void ln_split(const float* __restrict__ x, const float* __restrict__ g,
                         const float* __restrict__ b, bf16* __restrict__ oh,
                         bf16* __restrict__ ol) {
    __shared__ float red[32];
    __shared__ float s_mean, s_rstd;
    int row = blockIdx.x;
    int tid = threadIdx.x;
    float2 v = *(const float2*)(x + (size_t)row * D_DIM + tid * 2);

    float sum = v.x + v.y;
    #pragma unroll
    for (int o = 16; o > 0; o >>= 1) sum += __shfl_down_sync(0xffffffffu, sum, o);
    if ((tid & 31) == 0) red[tid >> 5] = sum;
    __syncthreads();
    if (tid < 32) {
        float t = (tid < 8) ? red[tid] : 0.f;
        #pragma unroll
        for (int o = 4; o > 0; o >>= 1) t += __shfl_down_sync(0xffffffffu, t, o);
        if (tid == 0) s_mean = t * (1.f / D_DIM);
    }
    __syncthreads();
    float mean = s_mean;
    float d0 = v.x - mean, d1 = v.y - mean;

    float vs = d0 * d0 + d1 * d1;
    #pragma unroll
    for (int o = 16; o > 0; o >>= 1) vs += __shfl_down_sync(0xffffffffu, vs, o);
    if ((tid & 31) == 0) red[tid >> 5] = vs;
    __syncthreads();
    if (tid < 32) {
        float t = (tid < 8) ? red[tid] : 0.f;
        #pragma unroll
        for (int o = 4; o > 0; o >>= 1) t += __shfl_down_sync(0xffffffffu, t, o);
        if (tid == 0) s_rstd = rsqrtf(t * (1.f / D_DIM) + EPS_LN);
    }
    __syncthreads();
    float rstd = s_rstd;

    int c = tid * 2;
    float2 gg = *(const float2*)(g + c);
    float2 bb = *(const float2*)(b + c);
    float ox = d0 * rstd * gg.x + bb.x;
    float oy = d1 * rstd * gg.y + bb.y;
    uint32_t hp, lp;
    split2(ox, oy, hp, lp);
    *(uint32_t*)(oh + (size_t)row * D_DIM + c) = hp;
    *(uint32_t*)(ol + (size_t)row * D_DIM + c) = lp;
}

// ---------------- cp.async split-bf16 GEMM ----------------
// A split [M][K_TOT] bf16, B split [N][K_TOT] bf16 (pre-transposed).
// EPI: 0 = bias -> qkv routing (qk split / vt split)
//      1 = bias + GELU -> split store (Ch/Cl)
//      2 = bias + residual(res fp32) -> fp32 Cf
template <int BN, int K_TOT, int EPI>
__global__ void __launch_bounds__(256, 2)
gemm_cp(const bf16* __restrict__ Ah, const bf16* __restrict__ Al,
        const bf16* __restrict__ Bh, const bf16* __restrict__ Bl,
        const float* __restrict__ bias, const float* __restrict__ res,
        float* __restrict__ Cf, bf16* __restrict__ Ch, bf16* __restrict__ Cl,
        bf16* __restrict__ Vh, bf16* __restrict__ Vl, int N) {
    constexpr int WARPS_N = BN / 32;
    constexpr int WARPS_M = 8 / WARPS_N;
    constexpr int WM = 128 / WARPS_M;
    constexpr int MI = WM / 16;
    constexpr int A_SZ = 128 * 80;
    constexpr int B_SZ = BN * 80;
    constexpr int B_OFF = 2 * A_SZ;
    constexpr int BUF = 2 * A_SZ + 2 * B_SZ;
    constexpr int NS = K_TOT / 32;

    extern __shared__ __align__(16) char smx[];
    const uint32_t sbase = smem_u32(smx);

    int tid = threadIdx.x;
    int wid = tid >> 5;
    int l = tid & 31;
    int bm = blockIdx.y * 128, bn = blockIdx.x * BN;
    int warp_m = wid / WARPS_N, warp_n = wid % WARPS_N;

    float d[MI][4][4];
    #pragma unroll
    for (int i = 0; i < MI; i++)
        #pragma unroll
        for (int j = 0; j < 4; j++)
            #pragma unroll
            for (int k = 0; k < 4; k++) d[i][j][k] = 0.f;

    int lb = l & 15;
    uint32_t a_rel = (uint32_t)(warp_m * WM + lb) * 80 + (uint32_t)(l >> 4) * 16;
    uint32_t b_rel = B_OFF + (uint32_t)(warp_n * 32 + (l >> 4) * 8 + (l & 7)) * 80 +
                     (uint32_t)((l >> 3) & 1) * 16;

    // loader indices (16-byte chunk = 8 bf16 elements)
    int a_cc = tid & 3, a_row = tid >> 2;
    constexpr int BCH = BN * 4;

    auto issue = [&](int s) {
        int k0 = s * 32;
        uint32_t bufb = sbase + (uint32_t)((s & 1) * BUF);
        #pragma unroll
        for (int t = 0; t < 2; t++) {
            int row = a_row + t * 64;
            size_t so = (size_t)(bm + row) * K_TOT + k0 + a_cc * 8;
            uint32_t dst = bufb + (uint32_t)(row * 80 + a_cc * 16);
            CP16(dst, Ah + so);
            CP16(dst + A_SZ, Al + so);
        }
        #pragma unroll
        for (int t = 0; t < BCH / 256; t++) {
            int c = tid + t * 256;
            int cc = c & 3, row = c >> 2;
            size_t so = (size_t)(bn + row) * K_TOT + k0 + cc * 8;
            uint32_t dst = bufb + B_OFF + (uint32_t)(row * 80 + cc * 16);
            CP16(dst, Bh + so);
            CP16(dst + B_SZ, Bl + so);
        }
    };

    issue(0); CP_COMMIT();

    for (int s = 0; s < NS; s++) {
        if (s + 1 < NS) { issue(s + 1); CP_COMMIT(); CP_WAIT1(); }
        else CP_WAIT0();
        __syncthreads();

        uint32_t cb = sbase + (uint32_t)((s & 1) * BUF);
        #pragma unroll
        for (int ks = 0; ks < 2; ks++) {
            uint32_t bh[4][2], blo[4][2];
            #pragma unroll
            for (int pj = 0; pj < 2; pj++) {
                uint32_t ba = cb + b_rel + pj * 16 * 80 + ks * 32;
                LDMATRIX_X4(bh[2 * pj][0], bh[2 * pj][1], bh[2 * pj + 1][0], bh[2 * pj + 1][1], ba);
                LDMATRIX_X4(blo[2 * pj][0], blo[2 * pj][1], blo[2 * pj + 1][0], blo[2 * pj + 1][1], ba + B_SZ);
            }
            #pragma unroll
            for (int mi = 0; mi < MI; mi++) {
                uint32_t ah[4], al[4];
                uint32_t aa = cb + a_rel + mi * 16 * 80 + ks * 32;
                LDMATRIX_X4(ah[0], ah[1], ah[2], ah[3], aa);
                LDMATRIX_X4(al[0], al[1], al[2], al[3], aa + A_SZ);
                #pragma unroll
                for (int nj = 0; nj < 4; nj++) {
                    MMA_BF16(d[mi][nj], ah, bh[nj]);
                    MMA_BF16(d[mi][nj], ah, blo[nj]);
                    MMA_BF16(d[mi][nj], al, bh[nj]);
                }
            }
        }
        __syncthreads();
    }

    // ---- epilogue ----
    #pragma unroll
    for (int mi = 0; mi < MI; mi++) {
        int row0 = bm + warp_m * WM + mi * 16 + (l >> 2);
        #pragma unroll
        for (int nj = 0; nj < 4; nj++) {
            int col = bn + warp_n * 32 + nj * 8 + (l & 3) * 2;
            float2 bb = *(const float2*)(bias + col);
            #pragma unroll
            for (int half = 0; half < 2; half++) {
                int row = row0 + half * 8;
                float vx = d[mi][nj][half * 2 + 0] + bb.x;
                float vy = d[mi][nj][half * 2 + 1] + bb.y;
                if (EPI == 0) {
                    if (col < 1024) {
                        uint32_t hp, lp;
                        split2(vx, vy, hp, lp);
                        *(uint32_t*)(Ch + (size_t)row * 1024 + col) = hp;
                        *(uint32_t*)(Cl + (size_t)row * 1024 + col) = lp;
                    } else {
                        int hc = col - 1024;
                        bf16 hx = __float2bfloat16(vx);
                        bf16 lx = __float2bfloat16(vx - __bfloat162float(hx));
                        bf16 hy = __float2bfloat16(vy);
                        bf16 ly = __float2bfloat16(vy - __bfloat162float(hy));
                        size_t i0 = (size_t)hc * S_LEN + row;
                        Vh[i0] = hx; Vl[i0] = lx;
                        Vh[i0 + S_LEN] = hy; Vl[i0 + S_LEN] = ly;
                    }
                } else if (EPI == 1) {
                    vx = 0.5f * vx * (1.f + erff(vx * 0.70710678118654752f));
                    vy = 0.5f * vy * (1.f + erff(vy * 0.70710678118654752f));
                    uint32_t hp, lp;
                    split2(vx, vy, hp, lp);
                    *(uint32_t*)(Ch + (size_t)row * N + col) = hp;
                    *(uint32_t*)(Cl + (size_t)row * N + col) = lp;
                } else {
                    float2 rr = *(const float2*)(res + (size_t)row * N + col);
                    float2 o2; o2.x = vx + rr.x; o2.y = vy + rr.y;
                    *(float2*)(Cf + (size_t)row * N + col) = o2;
                }
            }
        }
    }
}

// ---------------- cp.async flash attention ----------------
#define AST 144
#define QSZ (128 * AST)
#define KSZ (64 * AST)
#define KVBUF (4 * KSZ)
#define KV0 (2 * QSZ)
#define ATT_SMEM (KV0 + 2 * KVBUF)

__global__ void __launch_bounds__(256, 2)
attn_cp(const bf16* __restrict__ QKh, const bf16* __restrict__ QKl,
        const bf16* __restrict__ Vth, const bf16* __restrict__ Vtl,
        bf16* __restrict__ AOh, bf16* __restrict__ AOl) {
    extern __shared__ char sm[];
    const uint32_t sbase = smem_u32(sm);

    int qb = (int)gridDim.x - 1 - (int)blockIdx.x;   // heavy blocks first
    int h = blockIdx.y;
    int tid = threadIdx.x;
    int w = tid >> 5;
    int l = tid & 31;
    int lb = l & 15;

    int q_cc = tid & 7, q_row = tid >> 3;
    auto issueQ = [&]() {
        #pragma unroll
        for (int t = 0; t < 4; t++) {
            int row = q_row + t * 32;
            size_t so = (size_t)(qb * 128 + row) * 1024 + h * 64 + q_cc * 8;
            uint32_t dst = sbase + (uint32_t)(row * AST + q_cc * 16);
            CP16(dst, QKh + so);
            CP16(dst + QSZ, QKl + so);
        }
    };
    auto issueKV = [&](int kb) {
        uint32_t base = sbase + KV0 + (uint32_t)((kb & 1) * KVBUF);
        #pragma unroll
        for (int t = 0; t < 2; t++) {
            int row = q_row + t * 32;
            uint32_t doff = (uint32_t)(row * AST + q_cc * 16);
            size_t sk = (size_t)(kb * 64 + row) * 1024 + 512 + h * 64 + q_cc * 8;
            CP16(base + doff, QKh + sk);
            CP16(base + KSZ + doff, QKl + sk);
            size_t sv = (size_t)(h * 64 + row) * S_LEN + kb * 64 + q_cc * 8;
            CP16(base + 2 * KSZ + doff, Vth + sv);
            CP16(base + 3 * KSZ + doff, Vtl + sv);
        }
    };

    issueQ();
    issueKV(0); CP_COMMIT();

    float o[8][4];
    #pragma unroll
    for (int j = 0; j < 8; j++)
        #pragma unroll
        for (int k = 0; k < 4; k++) o[j][k] = 0.f;
    float m0 = -1e30f, m1 = -1e30f, l0 = 0.f, l1 = 0.f;

    uint32_t aq = sbase + (uint32_t)((16 * w + lb) * AST) + (uint32_t)(l >> 4) * 16;
    uint32_t kv_rel = (uint32_t)(((l >> 4) * 8 + (l & 7)) * AST) + (uint32_t)((l >> 3) & 1) * 16;

    int row0g = qb * 128 + 16 * w + (l >> 2);
    int kb_max = 2 * qb + 1;

    for (int kb = 0; kb <= kb_max; kb++) {
        if (kb < kb_max) { issueKV(kb + 1); CP_COMMIT(); CP_WAIT1(); }
        else CP_WAIT0();
        __syncthreads();

        uint32_t kvb = sbase + KV0 + (uint32_t)((kb & 1) * KVBUF);
        uint32_t bk = kvb + kv_rel;
        uint32_t bv = kvb + 2 * KSZ + kv_rel;

        // ---- S = Q K^T (3-pass split) ----
        float s[8][4];
        #pragma unroll
        for (int j = 0; j < 8; j++)
            #pragma unroll
            for (int k = 0; k < 4; k++) s[j][k] = 0.f;
        #pragma unroll
        for (int ks = 0; ks < 4; ks++) {
            uint32_t ah[4], al[4];
            LDMATRIX_X4(ah[0], ah[1], ah[2], ah[3], aq + ks * 32);
            LDMATRIX_X4(al[0], al[1], al[2], al[3], aq + ks * 32 + QSZ);
            #pragma unroll
            for (int jp = 0; jp < 4; jp++) {
                uint32_t bh[2][2], blo[2][2];
                uint32_t ba = bk + jp * 16 * AST + ks * 32;
                LDMATRIX_X4(bh[0][0], bh[0][1], bh[1][0], bh[1][1], ba);
                LDMATRIX_X4(blo[0][0], blo[0][1], blo[1][0], blo[1][1], ba + KSZ);
                #pragma unroll
                for (int q = 0; q < 2; q++) {
                    int j = 2 * jp + q;
                    MMA_BF16(s[j], ah, bh[q]);
                    MMA_BF16(s[j], ah, blo[q]);
                    MMA_BF16(s[j], al, bh[q]);
                }
            }
        }

        // ---- scale + causal mask ----
        int cbase = kb * 64 + 2 * (l & 3);
        bool need_mask = (kb >= 2 * qb);
        #pragma unroll
        for (int j = 0; j < 8; j++) {
            #pragma unroll
            for (int k = 0; k < 4; k++) s[j][k] *= 0.125f;
            if (need_mask) {
                int c0 = cbase + 8 * j;
                if (c0 > row0g)     s[j][0] = -1e30f;
                if (c0 + 1 > row0g) s[j][1] = -1e30f;
                if (c0 > row0g + 8)     s[j][2] = -1e30f;
                if (c0 + 1 > row0g + 8) s[j][3] = -1e30f;
            }
        }

        // ---- online softmax ----
        float mn0 = m0, mn1 = m1;
        #pragma unroll
        for (int j = 0; j < 8; j++) {
            mn0 = fmaxf(mn0, fmaxf(s[j][0], s[j][1]));
            mn1 = fmaxf(mn1, fmaxf(s[j][2], s[j][3]));
        }
        mn0 = fmaxf(mn0, __shfl_xor_sync(0xffffffffu, mn0, 1));
        mn0 = fmaxf(mn0, __shfl_xor_sync(0xffffffffu, mn0, 2));
        mn1 = fmaxf(mn1, __shfl_xor_sync(0xffffffffu, mn1, 1));
        mn1 = fmaxf(mn1, __shfl_xor_sync(0xffffffffu, mn1, 2));
        float alpha0 = __expf(m0 - mn0);
        float alpha1 = __expf(m1 - mn1);
        m0 = mn0; m1 = mn1;
        float rs0 = 0.f, rs1 = 0.f;
        #pragma unroll
        for (int j = 0; j < 8; j++) {
            s[j][0] = __expf(s[j][0] - mn0);
            s[j][1] = __expf(s[j][1] - mn0);
            s[j][2] = __expf(s[j][2] - mn1);
            s[j][3] = __expf(s[j][3] - mn1);
            rs0 += s[j][0] + s[j][1];
            rs1 += s[j][2] + s[j][3];
        }
        l0 = l0 * alpha0 + rs0;
        l1 = l1 * alpha1 + rs1;
        #pragma unroll
        for (int j = 0; j < 8; j++) {
            o[j][0] *= alpha0; o[j][1] *= alpha0;
            o[j][2] *= alpha1; o[j][3] *= alpha1;
        }

        // ---- O += P @ V (3-pass) ----
        #pragma unroll
        for (int ks = 0; ks < 4; ks++) {
            uint32_t pa[4], pl[4];
            pa[0] = pack_bf16(s[2 * ks][0], s[2 * ks][1]);
            pa[1] = pack_bf16(s[2 * ks][2], s[2 * ks][3]);
            pa[2] = pack_bf16(s[2 * ks + 1][0], s[2 * ks + 1][1]);
            pa[3] = pack_bf16(s[2 * ks + 1][2], s[2 * ks + 1][3]);
            pl[0] = pack_bf16_lo(s[2 * ks][0], s[2 * ks][1], pa[0]);
            pl[1] = pack_bf16_lo(s[2 * ks][2], s[2 * ks][3], pa[1]);
            pl[2] = pack_bf16_lo(s[2 * ks + 1][0], s[2 * ks + 1][1], pa[2]);
            pl[3] = pack_bf16_lo(s[2 * ks + 1][2], s[2 * ks + 1][3], pa[3]);
            #pragma unroll
            for (int jp = 0; jp < 4; jp++) {
                uint32_t vh[2][2], vl[2][2];
                uint32_t va = bv + jp * 16 * AST + ks * 32;
                LDMATRIX_X4(vh[0][0], vh[0][1], vh[1][0], vh[1][1], va);
                LDMATRIX_X4(vl[0][0], vl[0][1], vl[1][0], vl[1][1], va + KSZ);
                #pragma unroll
                for (int q = 0; q < 2; q++) {
                    int j = 2 * jp + q;
                    MMA_BF16(o[j], pa, vh[q]);
                    MMA_BF16(o[j], pa, vl[q]);
                    MMA_BF16(o[j], pl, vh[q]);
                }
            }
        }
        __syncthreads();
    }

    // ---- finalize: split store attention output ----
    l0 += __shfl_xor_sync(0xffffffffu, l0, 1);
    l0 += __shfl_xor_sync(0xffffffffu, l0, 2);
    l1 += __shfl_xor_sync(0xffffffffu, l1, 1);
    l1 += __shfl_xor_sync(0xffffffffu, l1, 2);
    float inv0 = 1.f / l0, inv1 = 1.f / l1;
    #pragma unroll
    for (int j = 0; j < 8; j++) {
        int col = h * 64 + 8 * j + 2 * (l & 3);
        uint32_t hp, lp;
        split2(o[j][0] * inv0, o[j][1] * inv0, hp, lp);
        *(uint32_t*)(AOh + (size_t)row0g * D_DIM + col) = hp;
        *(uint32_t*)(AOl + (size_t)row0g * D_DIM + col) = lp;
        split2(o[j][2] * inv1, o[j][3] * inv1, hp, lp);
        *(uint32_t*)(AOh + (size_t)(row0g + 8) * D_DIM + col) = hp;
        *(uint32_t*)(AOl + (size_t)(row0g + 8) * D_DIM + col) = lp;
    }
}

// ---------------- launch ----------------
extern "C" void kernel_launch(void* const* d_in, const int* in_sizes, int n_in,
                              void* d_out, int out_size) {
    const float* x    = (const float*)d_in[0];
    const float* wqkv = (const float*)d_in[1];
    const float* bqkv = (const float*)d_in[2];
    const float* wout = (const float*)d_in[3];
    const float* bout = (const float*)d_in[4];
    const float* wff1 = (const float*)d_in[5];
    const float* bff1 = (const float*)d_in[6];
    const float* wff2 = (const float*)d_in[7];
    const float* bff2 = (const float*)d_in[8];
    const float* g1   = (const float*)d_in[9];
    const float* bt1  = (const float*)d_in[10];
    const float* g2   = (const float*)d_in[11];
    const float* bt2  = (const float*)d_in[12];
    float* out = (float*)d_out;

    bf16 *hh, *hl, *wqh, *wql, *woh, *wol, *w1h, *w1l, *w2h, *w2l;
    bf16 *qkh, *qkl, *vth, *vtl, *aoh, *aol, *h2h, *h2l, *ffh, *ffl;
    float *x1;
    cudaGetSymbolAddress((void**)&hh,  g_h_hi);   cudaGetSymbolAddress((void**)&hl,  g_h_lo);
    cudaGetSymbolAddress((void**)&wqh, g_wqkvT_hi); cudaGetSymbolAddress((void**)&wql, g_wqkvT_lo);
    cudaGetSymbolAddress((void**)&woh, g_woutT_hi); cudaGetSymbolAddress((void**)&wol, g_woutT_lo);
    cudaGetSymbolAddress((void**)&w1h, g_wff1T_hi); cudaGetSymbolAddress((void**)&w1l, g_wff1T_lo);
    cudaGetSymbolAddress((void**)&w2h, g_wff2T_hi); cudaGetSymbolAddress((void**)&w2l, g_wff2T_lo);
    cudaGetSymbolAddress((void**)&qkh, g_qk_hi);  cudaGetSymbolAddress((void**)&qkl, g_qk_lo);
    cudaGetSymbolAddress((void**)&vth, g_vt_hi);  cudaGetSymbolAddress((void**)&vtl, g_vt_lo);
    cudaGetSymbolAddress((void**)&aoh, g_ao_hi);  cudaGetSymbolAddress((void**)&aol, g_ao_lo);
    cudaGetSymbolAddress((void**)&h2h, g_h2_hi);  cudaGetSymbolAddress((void**)&h2l, g_h2_lo);
    cudaGetSymbolAddress((void**)&ffh, g_ff_hi);  cudaGetSymbolAddress((void**)&ffl, g_ff_lo);
    cudaGetSymbolAddress((void**)&x1,  g_x1);

    const int GS128 = 2 * (2 * 128 * 80 + 2 * 128 * 80);  // 81920
    const int GS64  = 2 * (2 * 128 * 80 + 2 * 64 * 80);   // 61440
    cudaFuncSetAttribute(gemm_cp<128, 512, 0>, cudaFuncAttributeMaxDynamicSharedMemorySize, GS128);
    cudaFuncSetAttribute(gemm_cp<128, 512, 1>, cudaFuncAttributeMaxDynamicSharedMemorySize, GS128);
    cudaFuncSetAttribute(gemm_cp<64, 512, 2>,  cudaFuncAttributeMaxDynamicSharedMemorySize, GS64);
    cudaFuncSetAttribute(gemm_cp<64, 1024, 2>, cudaFuncAttributeMaxDynamicSharedMemorySize, GS64);
    cudaFuncSetAttribute(attn_cp, cudaFuncAttributeMaxDynamicSharedMemorySize, ATT_SMEM);

    // 0) weight prep: [K][N] -> [N][K] split
    wprep<<<dim3(1536 / 32, 512 / 32), 256>>>(wqkv, wqh, wql, 512, 1536);
    wprep<<<dim3(512 / 32, 512 / 32), 256>>>(wout, woh, wol, 512, 512);
    wprep<<<dim3(1024 / 32, 512 / 32), 256>>>(wff1, w1h, w1l, 512, 1024);
    wprep<<<dim3(512 / 32, 1024 / 32), 256>>>(wff2, w2h, w2l, 1024, 512);

    // 1) h = LN1(x) -> split
    ln_split<<<S_LEN, 256>>>(x, g1, bt1, hh, hl);
    // 2) qkv = h @ w_qkv + b_qkv -> qk split + vt split
    gemm_cp<128, 512, 0><<<dim3(12, 32), 256, GS128>>>(hh, hl, wqh, wql, bqkv,
        nullptr, nullptr, qkh, qkl, vth, vtl, 1536);
    // 3) attention -> ao split
    attn_cp<<<dim3(S_LEN / 128, 8), 256, ATT_SMEM>>>(qkh, qkl, vth, vtl, aoh, aol);
    // 4) x1 = x + ao @ w_out + b_out  (fp32)
    gemm_cp<64, 512, 2><<<dim3(8, 32), 256, GS64>>>(aoh, aol, woh, wol, bout,
        x, x1, nullptr, nullptr, nullptr, nullptr, 512);
    // 5) h2 = LN2(x1) -> split
    ln_split<<<S_LEN, 256>>>(x1, g2, bt2, h2h, h2l);
    // 6) ff = gelu(h2 @ w_ff1 + b_ff1) -> split
    gemm_cp<128, 512, 1><<<dim3(8, 32), 256, GS128>>>(h2h, h2l, w1h, w1l, bff1,
        nullptr, nullptr, ffh, ffl, nullptr, nullptr, 1024);
    // 7) out = x1 + ff @ w_ff2 + b_ff2  (fp32)
    gemm_cp<64, 1024, 2><<<dim3(8, 32), 256, GS64>>>(ffh, ffl, w2h, w2l, bff2,
        x1, out, nullptr, nullptr, nullptr, nullptr, 512);
}

// round 8
// speedup vs baseline: 3.2741x; 1.2238x over previous
#include <cuda_runtime.h>
#include <cuda_bf16.h>
#include <math.h>
#include <stdint.h>

typedef __nv_bfloat16 bf16;

#define S_LEN 4096
#define D_DIM 512
#define FF_DIM 1024
#define EPS_LN 1e-5f

// ---------------- persistent scratch (no allocations) ----------------
__device__ bf16 g_h_hi [S_LEN * D_DIM],  g_h_lo [S_LEN * D_DIM];
__device__ bf16 g_wqkvT_hi[1536 * 512],  g_wqkvT_lo[1536 * 512];
__device__ bf16 g_woutT_hi[512 * 512],   g_woutT_lo[512 * 512];
__device__ bf16 g_wff1T_hi[1024 * 512],  g_wff1T_lo[1024 * 512];
__device__ bf16 g_wff2T_hi[512 * 1024],  g_wff2T_lo[512 * 1024];
__device__ bf16 g_qk_hi[S_LEN * 1024],   g_qk_lo[S_LEN * 1024];
__device__ bf16 g_vt_hi[512 * S_LEN],    g_vt_lo[512 * S_LEN];   // [h*64+dh][seq]
__device__ bf16 g_ao_hi[S_LEN * D_DIM],  g_ao_lo[S_LEN * D_DIM];
__device__ bf16 g_h2_hi[S_LEN * D_DIM],  g_h2_lo[S_LEN * D_DIM];
__device__ bf16 g_ff_hi[S_LEN * FF_DIM], g_ff_lo[S_LEN * FF_DIM];
__device__ float g_x1[S_LEN * D_DIM];
__device__ float g_po[640 * 128 * 64];    // split-K partial O (unnormalized)
__device__ float g_pml[640 * 256];        // per-row (m, l) per split

__device__ __forceinline__ uint32_t smem_u32(const void* p) {
    uint32_t a;
    asm("{ .reg .u64 t; cvta.to.shared.u64 t, %1; cvt.u32.u64 %0, t; }" : "=r"(a) : "l"(p));
    return a;
}

#define LDMATRIX_X4(r0, r1, r2, r3, a) \
    asm volatile("ldmatrix.sync.aligned.m8n8.x4.shared.b16 {%0,%1,%2,%3}, [%4];" \
        : "=r"(r0), "=r"(r1), "=r"(r2), "=r"(r3) : "r"(a))
#define MMA_BF16(d, a, b) \
    asm volatile("mma.sync.aligned.m16n8k16.row.col.f32.bf16.bf16.f32 " \
        "{%0,%1,%2,%3}, {%4,%5,%6,%7}, {%8,%9}, {%0,%1,%2,%3};" \
        : "+f"((d)[0]), "+f"((d)[1]), "+f"((d)[2]), "+f"((d)[3]) \
        : "r"((a)[0]), "r"((a)[1]), "r"((a)[2]), "r"((a)[3]), "r"((b)[0]), "r"((b)[1]))

#define CP16(dst, src) asm volatile("cp.async.cg.shared.global [%0], [%1], 16;" :: "r"(dst), "l"(src))
#define CP_COMMIT()    asm volatile("cp.async.commit_group;")
#define CP_WAIT1()     asm volatile("cp.async.wait_group 1;" ::: "memory")
#define CP_WAIT0()     asm volatile("cp.async.wait_group 0;" ::: "memory")

__device__ __forceinline__ void split2(float x, float y, uint32_t& hp, uint32_t& lp) {
    __nv_bfloat162 h = __floats2bfloat162_rn(x, y);
    float lx = x - __bfloat162float(__low2bfloat16(h));
    float ly = y - __bfloat162float(__high2bfloat16(h));
    __nv_bfloat162 l = __floats2bfloat162_rn(lx, ly);
    hp = *(uint32_t*)&h; lp = *(uint32_t*)&l;
}
__device__ __forceinline__ uint32_t pack_bf16(float x, float y) {
    __nv_bfloat162 h = __floats2bfloat162_rn(x, y);
    return *(uint32_t*)&h;
}
__device__ __forceinline__ uint32_t pack_bf16_lo(float x, float y, uint32_t hp) {
    __nv_bfloat162 h = *(__nv_bfloat162*)&hp;
    float lx = x - __bfloat162float(__low2bfloat16(h));
    float ly = y - __bfloat162float(__high2bfloat16(h));
    __nv_bfloat162 lo = __floats2bfloat162_rn(lx, ly);
    return *(uint32_t*)&lo;
}

// ---------------- weight prep: [K][N] fp32 -> [N][K] split bf16 ----------------
__global__ void wprep(const float* __restrict__ src, bf16* __restrict__ dh,
                      bf16* __restrict__ dl, int K, int N) {
    __shared__ float t[32][33];
    int k0 = blockIdx.y * 32, n0 = blockIdx.x * 32;
    int tx = threadIdx.x & 31, ty = threadIdx.x >> 5;
    #pragma unroll
    for (int i = 0; i < 32; i += 8)
        t[ty + i][tx] = src[(size_t)(k0 + ty + i) * N + n0 + tx];
    __syncthreads();
    #pragma unroll
    for (int i = 0; i < 32; i += 8) {
        float v = t[tx][ty + i];
        bf16 h = __float2bfloat16(v);
        bf16 l = __float2bfloat16(v - __bfloat162float(h));
        size_t idx = (size_t)(n0 + ty + i) * K + k0 + tx;
        dh[idx] = h; dl[idx] = l;
    }
}

// ---------------- LayerNorm -> split bf16 ----------------
__global__ void ln_split(const float* __restrict__ x, const float* __restrict__ g,
                         const float* __restrict__ b, bf16* __restrict__ oh,
                         bf16* __restrict__ ol) {
    __shared__ float red[32];
    __shared__ float s_mean, s_rstd;
    int row = blockIdx.x;
    int tid = threadIdx.x;
    float2 v = *(const float2*)(x + (size_t)row * D_DIM + tid * 2);

    float sum = v.x + v.y;
    #pragma unroll
    for (int o = 16; o > 0; o >>= 1) sum += __shfl_down_sync(0xffffffffu, sum, o);
    if ((tid & 31) == 0) red[tid >> 5] = sum;
    __syncthreads();
    if (tid < 32) {
        float t = (tid < 8) ? red[tid] : 0.f;
        #pragma unroll
        for (int o = 4; o > 0; o >>= 1) t += __shfl_down_sync(0xffffffffu, t, o);
        if (tid == 0) s_mean = t * (1.f / D_DIM);
    }
    __syncthreads();
    float mean = s_mean;
    float d0 = v.x - mean, d1 = v.y - mean;

    float vs = d0 * d0 + d1 * d1;
    #pragma unroll
    for (int o = 16; o > 0; o >>= 1) vs += __shfl_down_sync(0xffffffffu, vs, o);
    if ((tid & 31) == 0) red[tid >> 5] = vs;
    __syncthreads();
    if (tid < 32) {
        float t = (tid < 8) ? red[tid] : 0.f;
        #pragma unroll
        for (int o = 4; o > 0; o >>= 1) t += __shfl_down_sync(0xffffffffu, t, o);
        if (tid == 0) s_rstd = rsqrtf(t * (1.f / D_DIM) + EPS_LN);
    }
    __syncthreads();
    float rstd = s_rstd;

    int c = tid * 2;
    float2 gg = *(const float2*)(g + c);
    float2 bb = *(const float2*)(b + c);
    float ox = d0 * rstd * gg.x + bb.x;
    float oy = d1 * rstd * gg.y + bb.y;
    uint32_t hp, lp;
    split2(ox, oy, hp, lp);
    *(uint32_t*)(oh + (size_t)row * D_DIM + c) = hp;
    *(uint32_t*)(ol + (size_t)row * D_DIM + c) = lp;
}

// ---------------- cp.async split-bf16 GEMM ----------------
template <int BN, int K_TOT, int EPI>
__global__ void __launch_bounds__(256, 2)
gemm_cp(const bf16* __restrict__ Ah, const bf16* __restrict__ Al,
        const bf16* __restrict__ Bh, const bf16* __restrict__ Bl,
        const float* __restrict__ bias, const float* __restrict__ res,
        float* __restrict__ Cf, bf16* __restrict__ Ch, bf16* __restrict__ Cl,
        bf16* __restrict__ Vh, bf16* __restrict__ Vl, int N) {
    constexpr int WARPS_N = BN / 32;
    constexpr int WARPS_M = 8 / WARPS_N;
    constexpr int WM = 128 / WARPS_M;
    constexpr int MI = WM / 16;
    constexpr int A_SZ = 128 * 80;
    constexpr int B_SZ = BN * 80;
    constexpr int B_OFF = 2 * A_SZ;
    constexpr int BUF = 2 * A_SZ + 2 * B_SZ;
    constexpr int NS = K_TOT / 32;

    extern __shared__ __align__(16) char smx[];
    const uint32_t sbase = smem_u32(smx);

    int tid = threadIdx.x;
    int wid = tid >> 5;
    int l = tid & 31;
    int bm = blockIdx.y * 128, bn = blockIdx.x * BN;
    int warp_m = wid / WARPS_N, warp_n = wid % WARPS_N;

    float d[MI][4][4];
    #pragma unroll
    for (int i = 0; i < MI; i++)
        #pragma unroll
        for (int j = 0; j < 4; j++)
            #pragma unroll
            for (int k = 0; k < 4; k++) d[i][j][k] = 0.f;

    int lb = l & 15;
    uint32_t a_rel = (uint32_t)(warp_m * WM + lb) * 80 + (uint32_t)(l >> 4) * 16;
    uint32_t b_rel = B_OFF + (uint32_t)(warp_n * 32 + (l >> 4) * 8 + (l & 7)) * 80 +
                     (uint32_t)((l >> 3) & 1) * 16;

    int a_cc = tid & 3, a_row = tid >> 2;
    constexpr int BCH = BN * 4;

    auto issue = [&](int s) {
        int k0 = s * 32;
        uint32_t bufb = sbase + (uint32_t)((s & 1) * BUF);
        #pragma unroll
        for (int t = 0; t < 2; t++) {
            int row = a_row + t * 64;
            size_t so = (size_t)(bm + row) * K_TOT + k0 + a_cc * 8;
            uint32_t dst = bufb + (uint32_t)(row * 80 + a_cc * 16);
            CP16(dst, Ah + so);
            CP16(dst + A_SZ, Al + so);
        }
        #pragma unroll
        for (int t = 0; t < BCH / 256; t++) {
            int c = tid + t * 256;
            int cc = c & 3, row = c >> 2;
            size_t so = (size_t)(bn + row) * K_TOT + k0 + cc * 8;
            uint32_t dst = bufb + B_OFF + (uint32_t)(row * 80 + cc * 16);
            CP16(dst, Bh + so);
            CP16(dst + B_SZ, Bl + so);
        }
    };

    issue(0); CP_COMMIT();

    for (int s = 0; s < NS; s++) {
        if (s + 1 < NS) { issue(s + 1); CP_COMMIT(); CP_WAIT1(); }
        else CP_WAIT0();
        __syncthreads();

        uint32_t cb = sbase + (uint32_t)((s & 1) * BUF);
        #pragma unroll
        for (int ks = 0; ks < 2; ks++) {
            uint32_t bh[4][2], blo[4][2];
            #pragma unroll
            for (int pj = 0; pj < 2; pj++) {
                uint32_t ba = cb + b_rel + pj * 16 * 80 + ks * 32;
                LDMATRIX_X4(bh[2 * pj][0], bh[2 * pj][1], bh[2 * pj + 1][0], bh[2 * pj + 1][1], ba);
                LDMATRIX_X4(blo[2 * pj][0], blo[2 * pj][1], blo[2 * pj + 1][0], blo[2 * pj + 1][1], ba + B_SZ);
            }
            #pragma unroll
            for (int mi = 0; mi < MI; mi++) {
                uint32_t ah[4], al[4];
                uint32_t aa = cb + a_rel + mi * 16 * 80 + ks * 32;
                LDMATRIX_X4(ah[0], ah[1], ah[2], ah[3], aa);
                LDMATRIX_X4(al[0], al[1], al[2], al[3], aa + A_SZ);
                #pragma unroll
                for (int nj = 0; nj < 4; nj++) {
                    MMA_BF16(d[mi][nj], ah, bh[nj]);
                    MMA_BF16(d[mi][nj], ah, blo[nj]);
                    MMA_BF16(d[mi][nj], al, bh[nj]);
                }
            }
        }
        __syncthreads();
    }

    // ---- epilogue ----
    #pragma unroll
    for (int mi = 0; mi < MI; mi++) {
        int row0 = bm + warp_m * WM + mi * 16 + (l >> 2);
        #pragma unroll
        for (int nj = 0; nj < 4; nj++) {
            int col = bn + warp_n * 32 + nj * 8 + (l & 3) * 2;
            float2 bb = *(const float2*)(bias + col);
            #pragma unroll
            for (int half = 0; half < 2; half++) {
                int row = row0 + half * 8;
                float vx = d[mi][nj][half * 2 + 0] + bb.x;
                float vy = d[mi][nj][half * 2 + 1] + bb.y;
                if (EPI == 0) {
                    if (col < 1024) {
                        uint32_t hp, lp;
                        split2(vx, vy, hp, lp);
                        *(uint32_t*)(Ch + (size_t)row * 1024 + col) = hp;
                        *(uint32_t*)(Cl + (size_t)row * 1024 + col) = lp;
                    } else {
                        int hc = col - 1024;
                        bf16 hx = __float2bfloat16(vx);
                        bf16 lx = __float2bfloat16(vx - __bfloat162float(hx));
                        bf16 hy = __float2bfloat16(vy);
                        bf16 ly = __float2bfloat16(vy - __bfloat162float(hy));
                        size_t i0 = (size_t)hc * S_LEN + row;
                        Vh[i0] = hx; Vl[i0] = lx;
                        Vh[i0 + S_LEN] = hy; Vl[i0 + S_LEN] = ly;
                    }
                } else if (EPI == 1) {
                    vx = 0.5f * vx * (1.f + erff(vx * 0.70710678118654752f));
                    vy = 0.5f * vy * (1.f + erff(vy * 0.70710678118654752f));
                    uint32_t hp, lp;
                    split2(vx, vy, hp, lp);
                    *(uint32_t*)(Ch + (size_t)row * N + col) = hp;
                    *(uint32_t*)(Cl + (size_t)row * N + col) = lp;
                } else {
                    float2 rr = *(const float2*)(res + (size_t)row * N + col);
                    float2 o2; o2.x = vx + rr.x; o2.y = vy + rr.y;
                    *(float2*)(Cf + (size_t)row * N + col) = o2;
                }
            }
        }
    }
}

// ---------------- cp.async flash attention, split-K balanced ----------------
// 80 split-CTAs per head: qb 0-7 ->1 split, 8-15 ->2, 16-23 ->3, 24-31 ->4.
#define AST 144
#define QSZ (128 * AST)
#define KSZ (64 * AST)
#define KVBUF (4 * KSZ)
#define KV0 (2 * QSZ)
#define ATT_SMEM (KV0 + 2 * KVBUF)

__global__ void __launch_bounds__(256, 2)
attn_cp(const bf16* __restrict__ QKh, const bf16* __restrict__ QKl,
        const bf16* __restrict__ Vth, const bf16* __restrict__ Vtl,
        bf16* __restrict__ AOh, bf16* __restrict__ AOl,
        float* __restrict__ Po, float* __restrict__ Pml) {
    extern __shared__ char sm[];
    const uint32_t sbase = smem_u32(sm);

    int gx = (int)gridDim.x - 1 - (int)blockIdx.x;   // heavy (high qb) first
    int qb, sp, nsp;
    if (gx < 8)       { qb = gx;                 sp = 0;            nsp = 1; }
    else if (gx < 24) { qb = 8 + (gx - 8) / 2;   sp = (gx - 8) % 2; nsp = 2; }
    else if (gx < 48) { qb = 16 + (gx - 24) / 3; sp = (gx - 24) % 3; nsp = 3; }
    else              { qb = 24 + (gx - 48) / 4; sp = (gx - 48) % 4; nsp = 4; }
    int total = 2 * qb + 2;
    int chunk = (total + nsp - 1) / nsp;
    int kb_begin = sp * chunk;
    int kb_end = min(total, kb_begin + chunk);
    int pidx = gx * 8 + (int)blockIdx.y;

    int h = blockIdx.y;
    int tid = threadIdx.x;
    int w = tid >> 5;
    int l = tid & 31;
    int lb = l & 15;

    int q_cc = tid & 7, q_row = tid >> 3;
    auto issueQ = [&]() {
        #pragma unroll
        for (int t = 0; t < 4; t++) {
            int row = q_row + t * 32;
            size_t so = (size_t)(qb * 128 + row) * 1024 + h * 64 + q_cc * 8;
            uint32_t dst = sbase + (uint32_t)(row * AST + q_cc * 16);
            CP16(dst, QKh + so);
            CP16(dst + QSZ, QKl + so);
        }
    };
    auto issueKV = [&](int kb) {
        uint32_t base = sbase + KV0 + (uint32_t)((kb & 1) * KVBUF);
        #pragma unroll
        for (int t = 0; t < 2; t++) {
            int row = q_row + t * 32;
            uint32_t doff = (uint32_t)(row * AST + q_cc * 16);
            size_t sk = (size_t)(kb * 64 + row) * 1024 + 512 + h * 64 + q_cc * 8;
            CP16(base + doff, QKh + sk);
            CP16(base + KSZ + doff, QKl + sk);
            size_t sv = (size_t)(h * 64 + row) * S_LEN + kb * 64 + q_cc * 8;
            CP16(base + 2 * KSZ + doff, Vth + sv);
            CP16(base + 3 * KSZ + doff, Vtl + sv);
        }
    };

    issueQ();
    issueKV(kb_begin); CP_COMMIT();

    float o[8][4];
    #pragma unroll
    for (int j = 0; j < 8; j++)
        #pragma unroll
        for (int k = 0; k < 4; k++) o[j][k] = 0.f;
    float m0 = -1e30f, m1 = -1e30f, l0 = 0.f, l1 = 0.f;

    uint32_t aq = sbase + (uint32_t)((16 * w + lb) * AST) + (uint32_t)(l >> 4) * 16;
    uint32_t kv_rel = (uint32_t)(((l >> 4) * 8 + (l & 7)) * AST) + (uint32_t)((l >> 3) & 1) * 16;

    int row0g = qb * 128 + 16 * w + (l >> 2);

    for (int kb = kb_begin; kb < kb_end; kb++) {
        if (kb + 1 < kb_end) { issueKV(kb + 1); CP_COMMIT(); CP_WAIT1(); }
        else CP_WAIT0();
        __syncthreads();

        uint32_t kvb = sbase + KV0 + (uint32_t)((kb & 1) * KVBUF);
        uint32_t bk = kvb + kv_rel;
        uint32_t bv = kvb + 2 * KSZ + kv_rel;

        // ---- S = Q K^T (3-pass split) ----
        float s[8][4];
        #pragma unroll
        for (int j = 0; j < 8; j++)
            #pragma unroll
            for (int k = 0; k < 4; k++) s[j][k] = 0.f;
        #pragma unroll
        for (int ks = 0; ks < 4; ks++) {
            uint32_t ah[4], al[4];
            LDMATRIX_X4(ah[0], ah[1], ah[2], ah[3], aq + ks * 32);
            LDMATRIX_X4(al[0], al[1], al[2], al[3], aq + ks * 32 + QSZ);
            #pragma unroll
            for (int jp = 0; jp < 4; jp++) {
                uint32_t bh[2][2], blo[2][2];
                uint32_t ba = bk + jp * 16 * AST + ks * 32;
                LDMATRIX_X4(bh[0][0], bh[0][1], bh[1][0], bh[1][1], ba);
                LDMATRIX_X4(blo[0][0], blo[0][1], blo[1][0], blo[1][1], ba + KSZ);
                #pragma unroll
                for (int q = 0; q < 2; q++) {
                    int j = 2 * jp + q;
                    MMA_BF16(s[j], ah, bh[q]);
                    MMA_BF16(s[j], ah, blo[q]);
                    MMA_BF16(s[j], al, bh[q]);
                }
            }
        }

        // ---- scale + causal mask ----
        int cbase = kb * 64 + 2 * (l & 3);
        bool need_mask = (kb >= 2 * qb);
        #pragma unroll
        for (int j = 0; j < 8; j++) {
            #pragma unroll
            for (int k = 0; k < 4; k++) s[j][k] *= 0.125f;
            if (need_mask) {
                int c0 = cbase + 8 * j;
                if (c0 > row0g)     s[j][0] = -1e30f;
                if (c0 + 1 > row0g) s[j][1] = -1e30f;
                if (c0 > row0g + 8)     s[j][2] = -1e30f;
                if (c0 + 1 > row0g + 8) s[j][3] = -1e30f;
            }
        }

        // ---- online softmax ----
        float mn0 = m0, mn1 = m1;
        #pragma unroll
        for (int j = 0; j < 8; j++) {
            mn0 = fmaxf(mn0, fmaxf(s[j][0], s[j][1]));
            mn1 = fmaxf(mn1, fmaxf(s[j][2], s[j][3]));
        }
        mn0 = fmaxf(mn0, __shfl_xor_sync(0xffffffffu, mn0, 1));
        mn0 = fmaxf(mn0, __shfl_xor_sync(0xffffffffu, mn0, 2));
        mn1 = fmaxf(mn1, __shfl_xor_sync(0xffffffffu, mn1, 1));
        mn1 = fmaxf(mn1, __shfl_xor_sync(0xffffffffu, mn1, 2));
        float alpha0 = __expf(m0 - mn0);
        float alpha1 = __expf(m1 - mn1);
        m0 = mn0; m1 = mn1;
        float rs0 = 0.f, rs1 = 0.f;
        #pragma unroll
        for (int j = 0; j < 8; j++) {
            s[j][0] = __expf(s[j][0] - mn0);
            s[j][1] = __expf(s[j][1] - mn0);
            s[j][2] = __expf(s[j][2] - mn1);
            s[j][3] = __expf(s[j][3] - mn1);
            rs0 += s[j][0] + s[j][1];
            rs1 += s[j][2] + s[j][3];
        }
        l0 = l0 * alpha0 + rs0;
        l1 = l1 * alpha1 + rs1;
        #pragma unroll
        for (int j = 0; j < 8; j++) {
            o[j][0] *= alpha0; o[j][1] *= alpha0;
            o[j][2] *= alpha1; o[j][3] *= alpha1;
        }

        // ---- O += P @ V (3-pass) ----
        #pragma unroll
        for (int ks = 0; ks < 4; ks++) {
            uint32_t pa[4], pl[4];
            pa[0] = pack_bf16(s[2 * ks][0], s[2 * ks][1]);
            pa[1] = pack_bf16(s[2 * ks][2], s[2 * ks][3]);
            pa[2] = pack_bf16(s[2 * ks + 1][0], s[2 * ks + 1][1]);
            pa[3] = pack_bf16(s[2 * ks + 1][2], s[2 * ks + 1][3]);
            pl[0] = pack_bf16_lo(s[2 * ks][0], s[2 * ks][1], pa[0]);
            pl[1] = pack_bf16_lo(s[2 * ks][2], s[2 * ks][3], pa[1]);
            pl[2] = pack_bf16_lo(s[2 * ks + 1][0], s[2 * ks + 1][1], pa[2]);
            pl[3] = pack_bf16_lo(s[2 * ks + 1][2], s[2 * ks + 1][3], pa[3]);
            #pragma unroll
            for (int jp = 0; jp < 4; jp++) {
                uint32_t vh[2][2], vl[2][2];
                uint32_t va = bv + jp * 16 * AST + ks * 32;
                LDMATRIX_X4(vh[0][0], vh[0][1], vh[1][0], vh[1][1], va);
                LDMATRIX_X4(vl[0][0], vl[0][1], vl[1][0], vl[1][1], va + KSZ);
                #pragma unroll
                for (int q = 0; q < 2; q++) {
                    int j = 2 * jp + q;
                    MMA_BF16(o[j], pa, vh[q]);
                    MMA_BF16(o[j], pa, vl[q]);
                    MMA_BF16(o[j], pl, vh[q]);
                }
            }
        }
        __syncthreads();
    }

    // ---- finalize ----
    l0 += __shfl_xor_sync(0xffffffffu, l0, 1);
    l0 += __shfl_xor_sync(0xffffffffu, l0, 2);
    l1 += __shfl_xor_sync(0xffffffffu, l1, 1);
    l1 += __shfl_xor_sync(0xffffffffu, l1, 2);

    if (nsp == 1) {
        float inv0 = 1.f / l0, inv1 = 1.f / l1;
        #pragma unroll
        for (int j = 0; j < 8; j++) {
            int col = h * 64 + 8 * j + 2 * (l & 3);
            uint32_t hp, lp;
            split2(o[j][0] * inv0, o[j][1] * inv0, hp, lp);
            *(uint32_t*)(AOh + (size_t)row0g * D_DIM + col) = hp;
            *(uint32_t*)(AOl + (size_t)row0g * D_DIM + col) = lp;
            split2(o[j][2] * inv1, o[j][3] * inv1, hp, lp);
            *(uint32_t*)(AOh + (size_t)(row0g + 8) * D_DIM + col) = hp;
            *(uint32_t*)(AOl + (size_t)(row0g + 8) * D_DIM + col) = lp;
        }
    } else {
        float* po = Po + (size_t)pidx * 8192;
        float* pml = Pml + (size_t)pidx * 256;
        int r0 = 16 * w + (l >> 2);
        #pragma unroll
        for (int j = 0; j < 8; j++) {
            int c = 8 * j + 2 * (l & 3);
            float2 v0; v0.x = o[j][0]; v0.y = o[j][1];
            float2 v1; v1.x = o[j][2]; v1.y = o[j][3];
            *(float2*)(po + r0 * 64 + c) = v0;
            *(float2*)(po + (r0 + 8) * 64 + c) = v1;
        }
        if ((l & 3) == 0) {
            pml[r0 * 2] = m0; pml[r0 * 2 + 1] = l0;
            pml[(r0 + 8) * 2] = m1; pml[(r0 + 8) * 2 + 1] = l1;
        }
    }
}

// ---------------- split-K combine (qb >= 8) ----------------
__global__ void attn_combine(const float* __restrict__ Po, const float* __restrict__ Pml,
                             bf16* __restrict__ AOh, bf16* __restrict__ AOl) {
    int qb = 8 + (int)blockIdx.x;
    int h = blockIdx.y;
    int nsp = 1 + (qb >> 3);
    int base = (qb < 16) ? 8 + (qb - 8) * 2 : (qb < 24) ? 24 + (qb - 16) * 3 : 48 + (qb - 24) * 4;
    int tid = threadIdx.x;
    int row = tid >> 1;
    int c0 = (tid & 1) * 32;

    float mi[4], li[4];
    float mg = -1e30f;
    for (int i = 0; i < nsp; i++) {
        const float* pml = Pml + (size_t)((base + i) * 8 + h) * 256;
        mi[i] = pml[row * 2];
        li[i] = pml[row * 2 + 1];
        mg = fmaxf(mg, mi[i]);
    }
    float L = 0.f, wgt[4];
    for (int i = 0; i < nsp; i++) { wgt[i] = __expf(mi[i] - mg); L += li[i] * wgt[i]; }
    float invL = 1.f / L;

    size_t orow = (size_t)(qb * 128 + row) * D_DIM + h * 64;
    for (int c = c0; c < c0 + 32; c += 2) {
        float x = 0.f, y = 0.f;
        for (int i = 0; i < nsp; i++) {
            const float* p = Po + (size_t)((base + i) * 8 + h) * 8192 + row * 64 + c;
            x += p[0] * wgt[i];
            y += p[1] * wgt[i];
        }
        x *= invL; y *= invL;
        uint32_t hp, lp;
        split2(x, y, hp, lp);
        *(uint32_t*)(AOh + orow + c) = hp;
        *(uint32_t*)(AOl + orow + c) = lp;
    }
}

// ---------------- launch ----------------
extern "C" void kernel_launch(void* const* d_in, const int* in_sizes, int n_in,
                              void* d_out, int out_size) {
    const float* x    = (const float*)d_in[0];
    const float* wqkv = (const float*)d_in[1];
    const float* bqkv = (const float*)d_in[2];
    const float* wout = (const float*)d_in[3];
    const float* bout = (const float*)d_in[4];
    const float* wff1 = (const float*)d_in[5];
    const float* bff1 = (const float*)d_in[6];
    const float* wff2 = (const float*)d_in[7];
    const float* bff2 = (const float*)d_in[8];
    const float* g1   = (const float*)d_in[9];
    const float* bt1  = (const float*)d_in[10];
    const float* g2   = (const float*)d_in[11];
    const float* bt2  = (const float*)d_in[12];
    float* out = (float*)d_out;

    bf16 *hh, *hl, *wqh, *wql, *woh, *wol, *w1h, *w1l, *w2h, *w2l;
    bf16 *qkh, *qkl, *vth, *vtl, *aoh, *aol, *h2h, *h2l, *ffh, *ffl;
    float *x1, *po, *pml;
    cudaGetSymbolAddress((void**)&hh,  g_h_hi);   cudaGetSymbolAddress((void**)&hl,  g_h_lo);
    cudaGetSymbolAddress((void**)&wqh, g_wqkvT_hi); cudaGetSymbolAddress((void**)&wql, g_wqkvT_lo);
    cudaGetSymbolAddress((void**)&woh, g_woutT_hi); cudaGetSymbolAddress((void**)&wol, g_woutT_lo);
    cudaGetSymbolAddress((void**)&w1h, g_wff1T_hi); cudaGetSymbolAddress((void**)&w1l, g_wff1T_lo);
    cudaGetSymbolAddress((void**)&w2h, g_wff2T_hi); cudaGetSymbolAddress((void**)&w2l, g_wff2T_lo);
    cudaGetSymbolAddress((void**)&qkh, g_qk_hi);  cudaGetSymbolAddress((void**)&qkl, g_qk_lo);
    cudaGetSymbolAddress((void**)&vth, g_vt_hi);  cudaGetSymbolAddress((void**)&vtl, g_vt_lo);
    cudaGetSymbolAddress((void**)&aoh, g_ao_hi);  cudaGetSymbolAddress((void**)&aol, g_ao_lo);
    cudaGetSymbolAddress((void**)&h2h, g_h2_hi);  cudaGetSymbolAddress((void**)&h2l, g_h2_lo);
    cudaGetSymbolAddress((void**)&ffh, g_ff_hi);  cudaGetSymbolAddress((void**)&ffl, g_ff_lo);
    cudaGetSymbolAddress((void**)&x1,  g_x1);
    cudaGetSymbolAddress((void**)&po,  g_po);
    cudaGetSymbolAddress((void**)&pml, g_pml);

    const int GS128 = 2 * (2 * 128 * 80 + 2 * 128 * 80);  // 81920
    const int GS64  = 2 * (2 * 128 * 80 + 2 * 64 * 80);   // 61440
    cudaFuncSetAttribute(gemm_cp<128, 512, 0>, cudaFuncAttributeMaxDynamicSharedMemorySize, GS128);
    cudaFuncSetAttribute(gemm_cp<128, 512, 1>, cudaFuncAttributeMaxDynamicSharedMemorySize, GS128);
    cudaFuncSetAttribute(gemm_cp<64, 512, 2>,  cudaFuncAttributeMaxDynamicSharedMemorySize, GS64);
    cudaFuncSetAttribute(gemm_cp<64, 1024, 2>, cudaFuncAttributeMaxDynamicSharedMemorySize, GS64);
    cudaFuncSetAttribute(attn_cp, cudaFuncAttributeMaxDynamicSharedMemorySize, ATT_SMEM);

    // 0) weight prep: [K][N] -> [N][K] split
    wprep<<<dim3(1536 / 32, 512 / 32), 256>>>(wqkv, wqh, wql, 512, 1536);
    wprep<<<dim3(512 / 32, 512 / 32), 256>>>(wout, woh, wol, 512, 512);
    wprep<<<dim3(1024 / 32, 512 / 32), 256>>>(wff1, w1h, w1l, 512, 1024);
    wprep<<<dim3(512 / 32, 1024 / 32), 256>>>(wff2, w2h, w2l, 1024, 512);

    // 1) h = LN1(x) -> split
    ln_split<<<S_LEN, 256>>>(x, g1, bt1, hh, hl);
    // 2) qkv = h @ w_qkv + b_qkv -> qk split + vt split
    gemm_cp<128, 512, 0><<<dim3(12, 32), 256, GS128>>>(hh, hl, wqh, wql, bqkv,
        nullptr, nullptr, qkh, qkl, vth, vtl, 1536);
    // 3) attention, split-K balanced -> ao split (+ partials)
    attn_cp<<<dim3(80, 8), 256, ATT_SMEM>>>(qkh, qkl, vth, vtl, aoh, aol, po, pml);
    attn_combine<<<dim3(24, 8), 256>>>(po, pml, aoh, aol);
    // 4) x1 = x + ao @ w_out + b_out  (fp32)
    gemm_cp<64, 512, 2><<<dim3(8, 32), 256, GS64>>>(aoh, aol, woh, wol, bout,
        x, x1, nullptr, nullptr, nullptr, nullptr, 512);
    // 5) h2 = LN2(x1) -> split
    ln_split<<<S_LEN, 256>>>(x1, g2, bt2, h2h, h2l);
    // 6) ff = gelu(h2 @ w_ff1 + b_ff1) -> split
    gemm_cp<128, 512, 1><<<dim3(8, 32), 256, GS128>>>(h2h, h2l, w1h, w1l, bff1,
        nullptr, nullptr, ffh, ffl, nullptr, nullptr, 1024);
    // 7) out = x1 + ff @ w_ff2 + b_ff2  (fp32)
    gemm_cp<64, 1024, 2><<<dim3(8, 32), 256, GS64>>>(ffh, ffl, w2h, w2l, bff2,
        x1, out, nullptr, nullptr, nullptr, nullptr, 512);
}